// round 3
// baseline (speedup 1.0000x reference)
#include <cuda_runtime.h>
#include <stdint.h>

#define BT 512
#define CH 16
#define SLEN 8192
#define NWARP 16
#define NCHUNK (SLEN / CH)

__device__ float g_sum[4096];
__device__ int   g_cnt[4096];

// mp table: d==0 -> 0.1, d=1..5 -> 0.7^d, d>=6 -> FP_PEN(10)
__constant__ float c_mpv[8] = {0.1f, 0.7f, 0.49f, 0.343f, 0.2401f, 0.16807f, 10.0f, 10.0f};

__device__ __forceinline__ int blockScanFwdMax(int v, int lane, int wid, int* s_warp, int* total)
{
    int inc = v;
#pragma unroll
    for (int d = 1; d < 32; d <<= 1) {
        int o = __shfl_up_sync(0xffffffffu, inc, d);
        if (lane >= d) inc = max(inc, o);
    }
    int excl = __shfl_up_sync(0xffffffffu, inc, 1);
    if (lane == 0) excl = -1;
    if (lane == 31) s_warp[wid] = inc;
    __syncthreads();
    int wpre = -1, tot = -1;
#pragma unroll
    for (int w = 0; w < NWARP; w++) {
        int t = s_warp[w];
        tot = max(tot, t);
        if (w < wid) wpre = max(wpre, t);
    }
    __syncthreads();
    *total = tot;
    return max(wpre, excl);
}

__device__ __forceinline__ int blockScanBwdMax(int v, int lane, int wid, int* s_warp)
{
    int inc = v;
#pragma unroll
    for (int d = 1; d < 32; d <<= 1) {
        int o = __shfl_down_sync(0xffffffffu, inc, d);
        if (lane < 32 - d) inc = max(inc, o);
    }
    int excl = __shfl_down_sync(0xffffffffu, inc, 1);
    if (lane == 31) excl = -1;
    if (lane == 0) s_warp[wid] = inc;
    __syncthreads();
    int wpre = -1;
#pragma unroll
    for (int w = 0; w < NWARP; w++) {
        if (w > wid) wpre = max(wpre, s_warp[w]);
    }
    __syncthreads();
    return max(wpre, excl);
}

__global__ void __launch_bounds__(BT, 2)
pal_row_kernel(const float4* __restrict__ logits4, const int* __restrict__ labels)
{
    __shared__ float s_ce[NCHUNK * (CH + 1)];            // padded: conflict-free chunk reads
    __shared__ __align__(16) unsigned char s_pl[SLEN];   // pred | (labenc<<4)
    __shared__ int s_warp[NWARP];
    __shared__ float s_racc[NWARP];
    __shared__ int s_rcnt[NWARP];

    const int row = blockIdx.x;
    const int tid = threadIdx.x;
    const int lane = tid & 31;
    const int wid = tid >> 5;

    const float4* lrow = logits4 + (size_t)row * SLEN;
    const int* labrow = labels + (size_t)row * SLEN;

    // ---- Pass A: coalesced load, argmax + weighted CE -> SMEM ----
#pragma unroll 4
    for (int k = 0; k < SLEN / BT; k++) {
        int i = tid + k * BT;
        float4 x = lrow[i];
        int lab = labrow[i];
        float best = x.x; int pred = 0;
        if (x.y > best) { best = x.y; pred = 1; }
        if (x.z > best) { best = x.z; pred = 2; }
        if (x.w > best) { best = x.w; pred = 3; }
        float e = __expf(x.x - best) + __expf(x.y - best) + __expf(x.z - best) + __expf(x.w - best);
        float lse = best + __logf(e);
        bool valid = ((unsigned)lab) < 4u;
        int labi = valid ? lab : 0;
        float xl = (labi == 0) ? x.x : (labi == 1) ? x.y : (labi == 2) ? x.z : x.w;
        float w = (labi >= 2) ? 30.0f : 1.0f;
        float ce = (lse - xl) * w;
        int labenc = valid ? lab : 6;
        s_ce[(i >> 4) * (CH + 1) + (i & 15)] = ce;
        s_pl[i] = (unsigned char)(pred | (labenc << 4));
    }
    __syncthreads();

    // ---- chunk summaries ----
    const int base = tid * CH;
    uint4 pbv = *(const uint4*)(s_pl + base);
    unsigned pk[4] = { pbv.x, pbv.y, pbv.z, pbv.w };

    int vstate = -1;
    int l2t = -1, l3t = -1, l2p = -1, l3p = -1;
    int f2t = -1, f3t = -1, f2p = -1, f3p = -1;
#pragma unroll
    for (int j = 0; j < CH; j++) {
        unsigned b = (pk[j >> 2] >> ((j & 3) * 8)) & 0xffu;
        int pred = b & 15;
        int lab = (int)(b >> 4);
        int g = base + j;
        if (lab < 4) vstate = (g << 2) | ((pred & 1) << 1) | (lab & 1);
        if (lab == 2) { l2t = g; if (f2t < 0) f2t = g; }
        if (lab == 3) { l3t = g; if (f3t < 0) f3t = g; }
        if (pred == 2) { l2p = g; if (f2p < 0) f2p = g; }
        if (pred == 3) { l3p = g; if (f3p < 0) f3p = g; }
    }

    // ---- block scans: 5 forward, 4 backward ----
    int tdum, tot2t, tot3t, tot2p, tot3p;
    int pstate = blockScanFwdMax(vstate, lane, wid, s_warp, &tdum);
    int p2t = blockScanFwdMax(l2t, lane, wid, s_warp, &tot2t);
    int p3t = blockScanFwdMax(l3t, lane, wid, s_warp, &tot3t);
    int p2p = blockScanFwdMax(l2p, lane, wid, s_warp, &tot2p);
    int p3p = blockScanFwdMax(l3p, lane, wid, s_warp, &tot3p);
    int n2t = blockScanBwdMax(f2t < 0 ? -1 : (SLEN - 1 - f2t), lane, wid, s_warp);
    int n3t = blockScanBwdMax(f3t < 0 ? -1 : (SLEN - 1 - f3t), lane, wid, s_warp);
    int n2p = blockScanBwdMax(f2p < 0 ? -1 : (SLEN - 1 - f2p), lane, wid, s_warp);
    int n3p = blockScanBwdMax(f3p < 0 ? -1 : (SLEN - 1 - f3p), lane, wid, s_warp);

    const bool has2t = tot2t >= 0, has3t = tot3t >= 0, has2p = tot2p >= 0, has3p = tot3p >= 0;

    const int BIGN = 1 << 28;
    int nx2t = (n2t >= 0) ? (SLEN - 1 - n2t) : BIGN;
    int nx3t = (n3t >= 0) ? (SLEN - 1 - n3t) : BIGN;
    int nx2p = (n2p >= 0) ? (SLEN - 1 - n2p) : BIGN;
    int nx3p = (n3p >= 0) ? (SLEN - 1 - n3p) : BIGN;

    // ---- backward in-chunk pass: pack 4x saturated distances (4 bits each) ----
    unsigned dbp[CH / 2];
#pragma unroll
    for (int j = CH - 1; j >= 0; j--) {
        unsigned b = (pk[j >> 2] >> ((j & 3) * 8)) & 0xffu;
        int pred = b & 15;
        int lab = (int)(b >> 4);
        int g = base + j;
        if (lab == 2) nx2t = g;
        if (lab == 3) nx3t = g;
        if (pred == 2) nx2p = g;
        if (pred == 3) nx3p = g;
        unsigned d0 = (unsigned)min(nx2t - g, 7);
        unsigned d1 = (unsigned)min(nx3t - g, 7);
        unsigned d2 = (unsigned)min(nx2p - g, 7);
        unsigned d3 = (unsigned)min(nx3p - g, 7);
        unsigned p16 = d0 | (d1 << 4) | (d2 << 8) | (d3 << 12);
        if (j & 1) dbp[j >> 1] = p16 << 16;
        else       dbp[j >> 1] |= p16;
    }

    // ---- forward in-chunk pass: state machine + multipliers + accumulate ----
    int pm = 0, tm = 0;
    if (pstate >= 0) { pm = (pstate >> 1) & 1; tm = pstate & 1; }
    int la2t = (p2t >= 0) ? p2t : -BIGN;
    int la3t = (p3t >= 0) ? p3t : -BIGN;
    int la2p = (p2p >= 0) ? p2p : -BIGN;
    int la3p = (p3p >= 0) ? p3p : -BIGN;

    float acc = 0.0f; int cnt = 0;
#pragma unroll
    for (int j = 0; j < CH; j++) {
        unsigned b = (pk[j >> 2] >> ((j & 3) * 8)) & 0xffu;
        int pred = b & 15;
        int lab = (int)(b >> 4);
        int g = base + j;
        bool valid = lab < 4;
        float pbm = 1.0f;
        if (valid && ((pred == 2 && pm == 0) || (pred == 3 && pm == 1))) pbm = 100.0f;
        if (valid && ((lab == 2 && tm == 1 && pred == 2) || (lab == 3 && tm == 0 && pred == 3))) pbm *= 0.1f;
        if (valid) { pm = pred & 1; tm = lab & 1; }
        if (lab == 2) la2t = g;
        if (lab == 3) la3t = g;
        if (pred == 2) la2p = g;
        if (pred == 3) la3p = g;
        unsigned p16 = (dbp[j >> 1] >> ((j & 1) * 16)) & 0xffffu;
        int d2t = min(min(g - la2t, 7), (int)(p16 & 15));
        int d3t = min(min(g - la3t, 7), (int)((p16 >> 4) & 15));
        int d2p = min(min(g - la2p, 7), (int)((p16 >> 8) & 15));
        int d3p = min(min(g - la3p, 7), (int)((p16 >> 12) & 15));
        float mult = pbm;
        mult *= (pred == 2) ? (has2t ? c_mpv[d2t] : 20.0f) : 1.0f;
        mult *= (lab == 2) ? (has2p ? ((d2p > 5) ? 2.0f : 1.0f) : 3.0f) : 1.0f;
        mult *= (pred == 3) ? (has3t ? c_mpv[d3t] : 20.0f) : 1.0f;
        mult *= (lab == 3) ? (has3p ? ((d3p > 5) ? 2.0f : 1.0f) : 3.0f) : 1.0f;
        if (valid) {
            float ce = s_ce[tid * (CH + 1) + j];
            acc += ce * mult;
            cnt += 1;
        }
    }

    // ---- deterministic block reduce ----
#pragma unroll
    for (int d = 16; d > 0; d >>= 1) {
        acc += __shfl_down_sync(0xffffffffu, acc, d);
        cnt += __shfl_down_sync(0xffffffffu, cnt, d);
    }
    if (lane == 0) { s_racc[wid] = acc; s_rcnt[wid] = cnt; }
    __syncthreads();
    if (wid == 0) {
        float a = (lane < NWARP) ? s_racc[lane] : 0.0f;
        int c = (lane < NWARP) ? s_rcnt[lane] : 0;
#pragma unroll
        for (int d = 8; d > 0; d >>= 1) {
            a += __shfl_down_sync(0xffffffffu, a, d);
            c += __shfl_down_sync(0xffffffffu, c, d);
        }
        if (lane == 0) { g_sum[row] = a; g_cnt[row] = c; }
    }
}

__global__ void pal_final_kernel(float* out, int B)
{
    __shared__ float s_a[16];
    __shared__ int s_c[16];
    int tid = threadIdx.x, lane = tid & 31, wid = tid >> 5;
    float a = 0.0f; int c = 0;
    for (int i = tid; i < B; i += blockDim.x) { a += g_sum[i]; c += g_cnt[i]; }
#pragma unroll
    for (int d = 16; d > 0; d >>= 1) {
        a += __shfl_down_sync(0xffffffffu, a, d);
        c += __shfl_down_sync(0xffffffffu, c, d);
    }
    if (lane == 0) { s_a[wid] = a; s_c[wid] = c; }
    __syncthreads();
    if (wid == 0) {
        int nw = blockDim.x >> 5;
        a = (lane < nw) ? s_a[lane] : 0.0f;
        c = (lane < nw) ? s_c[lane] : 0;
#pragma unroll
        for (int d = 8; d > 0; d >>= 1) {
            a += __shfl_down_sync(0xffffffffu, a, d);
            c += __shfl_down_sync(0xffffffffu, c, d);
        }
        if (lane == 0) out[0] = a / fmaxf((float)c, 1.0f);
    }
}

extern "C" void kernel_launch(void* const* d_in, const int* in_sizes, int n_in,
                              void* d_out, int out_size)
{
    const float4* logits = (const float4*)d_in[0];
    const int* labels = (const int*)d_in[1];
    int B = in_sizes[1] / SLEN;
    pal_row_kernel<<<B, BT>>>(logits, labels);
    pal_final_kernel<<<1, 512>>>((float*)d_out, B);
}

// round 4
// speedup vs baseline: 1.8762x; 1.8762x over previous
#include <cuda_runtime.h>
#include <stdint.h>

#define BT 512
#define CH 16
#define SLEN 8192
#define NWARP 16
#define NCHUNK (SLEN / CH)

__device__ float g_sum[4096];
__device__ int   g_cnt[4096];
__device__ int   g_done = 0;

// mp table: d==0 -> 0.1, d=1..5 -> 0.7^d, d>=6 -> FP_PEN(10)
__constant__ float c_mpv[8] = {0.1f, 0.7f, 0.49f, 0.343f, 0.2401f, 0.16807f, 10.0f, 10.0f};

// last set-byte index within 16 bytes (4 LE words), -1 if none
__device__ __forceinline__ int lastByte(unsigned m0, unsigned m1, unsigned m2, unsigned m3)
{
    unsigned w; int k;
    if (m3)      { w = m3; k = 3; }
    else if (m2) { w = m2; k = 2; }
    else if (m1) { w = m1; k = 1; }
    else if (m0) { w = m0; k = 0; }
    else return -1;
    return k * 4 + (3 - (__clz(w) >> 3));
}

// first set-byte index within 16 bytes, -1 if none
__device__ __forceinline__ int firstByte(unsigned m0, unsigned m1, unsigned m2, unsigned m3)
{
    unsigned w; int k;
    if (m0)      { w = m0; k = 0; }
    else if (m1) { w = m1; k = 1; }
    else if (m2) { w = m2; k = 2; }
    else { w = m3; k = 3; if (!m3) return -1; }
    return k * 4 + ((__ffs(w) - 1) >> 3);
}

// warp-level inclusive prefix max -> returns exclusive; lane31 writes warp total
__device__ __forceinline__ int warpScanFwd(int v, int lane, int wid, int s, int (*s_scan)[NWARP])
{
    int inc = v;
#pragma unroll
    for (int d = 1; d < 32; d <<= 1) {
        int o = __shfl_up_sync(0xffffffffu, inc, d);
        if (lane >= d) inc = max(inc, o);
    }
    int excl = __shfl_up_sync(0xffffffffu, inc, 1);
    if (lane == 0) excl = -1;
    if (lane == 31) s_scan[s][wid] = inc;
    return excl;
}

__device__ __forceinline__ int warpScanBwd(int v, int lane, int wid, int s, int (*s_scan)[NWARP])
{
    int inc = v;
#pragma unroll
    for (int d = 1; d < 32; d <<= 1) {
        int o = __shfl_down_sync(0xffffffffu, inc, d);
        if (lane < 32 - d) inc = max(inc, o);
    }
    int excl = __shfl_down_sync(0xffffffffu, inc, 1);
    if (lane == 31) excl = -1;
    if (lane == 0) s_scan[s][wid] = inc;
    return excl;
}

__global__ void __launch_bounds__(BT, 2)
pal_row_kernel(const float4* __restrict__ logits4, const int* __restrict__ labels,
               float* __restrict__ out, int B)
{
    __shared__ float s_ce[NCHUNK * (CH + 1)];            // padded chunk-major CE
    __shared__ __align__(16) unsigned char s_pl[SLEN];   // pred | (labenc<<4)
    __shared__ int s_scan[9][NWARP];
    __shared__ int s_pre[9][NWARP];
    __shared__ int s_tot[4];
    __shared__ float s_racc[NWARP];
    __shared__ int s_rcnt[NWARP];
    __shared__ int s_last;

    const int row = blockIdx.x;
    const int tid = threadIdx.x;
    const int lane = tid & 31;
    const int wid = tid >> 5;

    const float4* lrow = logits4 + (size_t)row * SLEN;
    const int* labrow = labels + (size_t)row * SLEN;

    // ---- Pass A: coalesced load, argmax + weighted CE -> SMEM ----
#pragma unroll 4
    for (int k = 0; k < SLEN / BT; k++) {
        int i = tid + k * BT;
        float4 x = lrow[i];
        int lab = labrow[i];
        float best = x.x; int pred = 0;
        if (x.y > best) { best = x.y; pred = 1; }
        if (x.z > best) { best = x.z; pred = 2; }
        if (x.w > best) { best = x.w; pred = 3; }
        float e = __expf(x.x - best) + __expf(x.y - best) + __expf(x.z - best) + __expf(x.w - best);
        float lse = best + __logf(e);
        bool valid = ((unsigned)lab) < 4u;
        int labi = valid ? lab : 0;
        float xl = (labi == 0) ? x.x : (labi == 1) ? x.y : (labi == 2) ? x.z : x.w;
        float w = (labi >= 2) ? 30.0f : 1.0f;
        s_ce[(i >> 4) * (CH + 1) + (i & 15)] = (lse - xl) * w;
        int labenc = valid ? lab : 6;
        s_pl[i] = (unsigned char)(pred | (labenc << 4));
    }
    __syncthreads();

    // ---- chunk summary via SIMD byte ops ----
    const int base = tid * CH;
    uint4 pbv = *(const uint4*)(s_pl + base);
    unsigned pk[4] = { pbv.x, pbv.y, pbv.z, pbv.w };

    unsigned v0 = __vcmpeq4(pk[0] & 0x40404040u, 0u);
    unsigned v1 = __vcmpeq4(pk[1] & 0x40404040u, 0u);
    unsigned v2 = __vcmpeq4(pk[2] & 0x40404040u, 0u);
    unsigned v3 = __vcmpeq4(pk[3] & 0x40404040u, 0u);
    unsigned t20 = __vcmpeq4(pk[0] & 0xf0f0f0f0u, 0x20202020u);
    unsigned t21 = __vcmpeq4(pk[1] & 0xf0f0f0f0u, 0x20202020u);
    unsigned t22 = __vcmpeq4(pk[2] & 0xf0f0f0f0u, 0x20202020u);
    unsigned t23 = __vcmpeq4(pk[3] & 0xf0f0f0f0u, 0x20202020u);
    unsigned t30 = __vcmpeq4(pk[0] & 0xf0f0f0f0u, 0x30303030u);
    unsigned t31 = __vcmpeq4(pk[1] & 0xf0f0f0f0u, 0x30303030u);
    unsigned t32 = __vcmpeq4(pk[2] & 0xf0f0f0f0u, 0x30303030u);
    unsigned t33 = __vcmpeq4(pk[3] & 0xf0f0f0f0u, 0x30303030u);
    unsigned p20 = __vcmpeq4(pk[0] & 0x0f0f0f0fu, 0x02020202u);
    unsigned p21 = __vcmpeq4(pk[1] & 0x0f0f0f0fu, 0x02020202u);
    unsigned p22 = __vcmpeq4(pk[2] & 0x0f0f0f0fu, 0x02020202u);
    unsigned p23 = __vcmpeq4(pk[3] & 0x0f0f0f0fu, 0x02020202u);
    unsigned p30 = __vcmpeq4(pk[0] & 0x0f0f0f0fu, 0x03030303u);
    unsigned p31 = __vcmpeq4(pk[1] & 0x0f0f0f0fu, 0x03030303u);
    unsigned p32 = __vcmpeq4(pk[2] & 0x0f0f0f0fu, 0x03030303u);
    unsigned p33 = __vcmpeq4(pk[3] & 0x0f0f0f0fu, 0x03030303u);

    // fwd scan inputs (last index in chunk, absolute; -1 none)
    int lv = lastByte(v0, v1, v2, v3);
    int vstate = -1;
    if (lv >= 0) {
        unsigned b = (pk[lv >> 2] >> ((lv & 3) * 8)) & 0xffu;
        vstate = ((base + lv) << 2) | ((b & 1) << 1) | ((b >> 4) & 1);
    }
    int lb;
    lb = lastByte(t20, t21, t22, t23); int l2t = lb < 0 ? -1 : base + lb;
    lb = lastByte(t30, t31, t32, t33); int l3t = lb < 0 ? -1 : base + lb;
    lb = lastByte(p20, p21, p22, p23); int l2p = lb < 0 ? -1 : base + lb;
    lb = lastByte(p30, p31, p32, p33); int l3p = lb < 0 ? -1 : base + lb;
    // bwd scan inputs (first index, reverse-encoded; -1 none)
    int fb;
    fb = firstByte(t20, t21, t22, t23); int f2t = fb < 0 ? -1 : (SLEN - 1 - (base + fb));
    fb = firstByte(t30, t31, t32, t33); int f3t = fb < 0 ? -1 : (SLEN - 1 - (base + fb));
    fb = firstByte(p20, p21, p22, p23); int f2p = fb < 0 ? -1 : (SLEN - 1 - (base + fb));
    fb = firstByte(p30, p31, p32, p33); int f3p = fb < 0 ? -1 : (SLEN - 1 - (base + fb));

    // ---- phase 1: warp-level scans (no barrier between them) ----
    int wx0 = warpScanFwd(vstate, lane, wid, 0, s_scan);
    int wx1 = warpScanFwd(l2t,    lane, wid, 1, s_scan);
    int wx2 = warpScanFwd(l3t,    lane, wid, 2, s_scan);
    int wx3 = warpScanFwd(l2p,    lane, wid, 3, s_scan);
    int wx4 = warpScanFwd(l3p,    lane, wid, 4, s_scan);
    int wx5 = warpScanBwd(f2t,    lane, wid, 5, s_scan);
    int wx6 = warpScanBwd(f3t,    lane, wid, 6, s_scan);
    int wx7 = warpScanBwd(f2p,    lane, wid, 7, s_scan);
    int wx8 = warpScanBwd(f3p,    lane, wid, 8, s_scan);
    __syncthreads();

    // ---- phase 2: 9 warps combine cross-warp in parallel ----
    if (wid < 9) {
        int v = (lane < NWARP) ? s_scan[wid][lane] : -1;
        if (wid < 5) {
            int inc = v;
#pragma unroll
            for (int d = 1; d < 16; d <<= 1) {
                int o = __shfl_up_sync(0xffffffffu, inc, d);
                if (lane >= d) inc = max(inc, o);
            }
            int ex = __shfl_up_sync(0xffffffffu, inc, 1);
            if (lane == 0) ex = -1;
            if (lane < NWARP) s_pre[wid][lane] = ex;
            if (lane == NWARP - 1 && wid >= 1) s_tot[wid - 1] = inc;
        } else {
            int inc = v;
#pragma unroll
            for (int d = 1; d < 16; d <<= 1) {
                int o = __shfl_down_sync(0xffffffffu, inc, d);
                if (lane < 32 - d) inc = max(inc, o);
            }
            int ex = __shfl_down_sync(0xffffffffu, inc, 1);
            if (lane == NWARP - 1) ex = -1;
            if (lane < NWARP) s_pre[wid][lane] = ex;
        }
    }
    __syncthreads();

    // ---- phase 3: combine ----
    const int pstate = max(wx0, s_pre[0][wid]);
    const int p2t = max(wx1, s_pre[1][wid]);
    const int p3t = max(wx2, s_pre[2][wid]);
    const int p2p = max(wx3, s_pre[3][wid]);
    const int p3p = max(wx4, s_pre[4][wid]);
    const int n2t = max(wx5, s_pre[5][wid]);
    const int n3t = max(wx6, s_pre[6][wid]);
    const int n2p = max(wx7, s_pre[7][wid]);
    const int n3p = max(wx8, s_pre[8][wid]);
    const bool has2t = s_tot[0] >= 0, has3t = s_tot[1] >= 0;
    const bool has2p = s_tot[2] >= 0, has3p = s_tot[3] >= 0;

    // ---- backward in-chunk pass: saturating distance counters, pack 4x4 bits ----
    int d2t = (n2t < 0) ? 7 : min(SLEN - 1 - n2t - (base + CH), 7);
    int d3t = (n3t < 0) ? 7 : min(SLEN - 1 - n3t - (base + CH), 7);
    int d2p = (n2p < 0) ? 7 : min(SLEN - 1 - n2p - (base + CH), 7);
    int d3p = (n3p < 0) ? 7 : min(SLEN - 1 - n3p - (base + CH), 7);
    unsigned dbp[CH / 2];
#pragma unroll
    for (int j = CH - 1; j >= 0; j--) {
        unsigned b = (pk[j >> 2] >> ((j & 3) * 8)) & 0xffu;
        int pred = b & 15;
        int lab = (int)(b >> 4);
        d2t = (lab == 2)  ? 0 : min(d2t + 1, 7);
        d3t = (lab == 3)  ? 0 : min(d3t + 1, 7);
        d2p = (pred == 2) ? 0 : min(d2p + 1, 7);
        d3p = (pred == 3) ? 0 : min(d3p + 1, 7);
        unsigned p16 = (unsigned)d2t | ((unsigned)d3t << 4) | ((unsigned)d2p << 8) | ((unsigned)d3p << 12);
        if (j & 1) dbp[j >> 1] = p16 << 16;
        else       dbp[j >> 1] |= p16;
    }

    // ---- forward in-chunk pass: state machine + multipliers + accumulate ----
    int pm = 0, tm = 0;
    if (pstate >= 0) { pm = (pstate >> 1) & 1; tm = pstate & 1; }
    int e2t = (p2t < 0) ? 7 : min(base - 1 - p2t, 7);
    int e3t = (p3t < 0) ? 7 : min(base - 1 - p3t, 7);
    int e2p = (p2p < 0) ? 7 : min(base - 1 - p2p, 7);
    int e3p = (p3p < 0) ? 7 : min(base - 1 - p3p, 7);

    float acc = 0.0f; int cnt = 0;
#pragma unroll
    for (int j = 0; j < CH; j++) {
        unsigned b = (pk[j >> 2] >> ((j & 3) * 8)) & 0xffu;
        int pred = b & 15;
        int lab = (int)(b >> 4);
        bool valid = lab < 4;
        float pbm = 1.0f;
        if (valid && ((pred == 2 && pm == 0) || (pred == 3 && pm == 1))) pbm = 100.0f;
        if (valid && ((lab == 2 && tm == 1 && pred == 2) || (lab == 3 && tm == 0 && pred == 3))) pbm *= 0.1f;
        if (valid) { pm = pred & 1; tm = lab & 1; }
        e2t = (lab == 2)  ? 0 : min(e2t + 1, 7);
        e3t = (lab == 3)  ? 0 : min(e3t + 1, 7);
        e2p = (pred == 2) ? 0 : min(e2p + 1, 7);
        e3p = (pred == 3) ? 0 : min(e3p + 1, 7);
        unsigned p16 = (dbp[j >> 1] >> ((j & 1) * 16)) & 0xffffu;
        int m2t = min(e2t, (int)(p16 & 15));
        int m3t = min(e3t, (int)((p16 >> 4) & 15));
        int m2p = min(e2p, (int)((p16 >> 8) & 15));
        int m3p = min(e3p, (int)((p16 >> 12) & 15));
        float mult = pbm;
        if (pred == 2) mult *= has2t ? c_mpv[m2t] : 20.0f;
        if (lab == 2)  mult *= has2p ? ((m2p > 5) ? 2.0f : 1.0f) : 3.0f;
        if (pred == 3) mult *= has3t ? c_mpv[m3t] : 20.0f;
        if (lab == 3)  mult *= has3p ? ((m3p > 5) ? 2.0f : 1.0f) : 3.0f;
        if (valid) {
            acc += s_ce[tid * (CH + 1) + j] * mult;
            cnt += 1;
        }
    }

    // ---- deterministic block reduce ----
#pragma unroll
    for (int d = 16; d > 0; d >>= 1) {
        acc += __shfl_down_sync(0xffffffffu, acc, d);
        cnt += __shfl_down_sync(0xffffffffu, cnt, d);
    }
    if (lane == 0) { s_racc[wid] = acc; s_rcnt[wid] = cnt; }
    __syncthreads();
    if (wid == 0) {
        float a = (lane < NWARP) ? s_racc[lane] : 0.0f;
        int c = (lane < NWARP) ? s_rcnt[lane] : 0;
#pragma unroll
        for (int d = 8; d > 0; d >>= 1) {
            a += __shfl_down_sync(0xffffffffu, a, d);
            c += __shfl_down_sync(0xffffffffu, c, d);
        }
        if (lane == 0) {
            g_sum[row] = a; g_cnt[row] = c;
            __threadfence();
            int old = atomicAdd(&g_done, 1);
            s_last = (old == (int)gridDim.x - 1) ? 1 : 0;
        }
    }
    __syncthreads();

    // ---- last block: fixed-order final reduce (graph-replay safe: resets g_done) ----
    if (s_last) {
        float a = 0.0f; int c = 0;
        for (int i = tid; i < B; i += BT) {
            a += __ldcg(&g_sum[i]);
            c += __ldcg(&g_cnt[i]);
        }
#pragma unroll
        for (int d = 16; d > 0; d >>= 1) {
            a += __shfl_down_sync(0xffffffffu, a, d);
            c += __shfl_down_sync(0xffffffffu, c, d);
        }
        if (lane == 0) { s_racc[wid] = a; s_rcnt[wid] = c; }
        __syncthreads();
        if (wid == 0) {
            a = (lane < NWARP) ? s_racc[lane] : 0.0f;
            c = (lane < NWARP) ? s_rcnt[lane] : 0;
#pragma unroll
            for (int d = 8; d > 0; d >>= 1) {
                a += __shfl_down_sync(0xffffffffu, a, d);
                c += __shfl_down_sync(0xffffffffu, c, d);
            }
            if (lane == 0) {
                out[0] = a / fmaxf((float)c, 1.0f);
                g_done = 0;
            }
        }
    }
}

extern "C" void kernel_launch(void* const* d_in, const int* in_sizes, int n_in,
                              void* d_out, int out_size)
{
    const float4* logits = (const float4*)d_in[0];
    const int* labels = (const int*)d_in[1];
    int B = in_sizes[1] / SLEN;
    pal_row_kernel<<<B, BT>>>(logits, labels, (float*)d_out, B);
}

// round 5
// speedup vs baseline: 3.1882x; 1.6993x over previous
#include <cuda_runtime.h>
#include <stdint.h>

#define BT 512
#define CH 16
#define SLEN 8192
#define NW 16

__device__ float g_sum[4096];
__device__ int   g_cnt[4096];
__device__ int   g_done = 0;

// idx = levelcount (0..6) + 8*noTrue. levelcount = 6-d (d<=5), 0 if d>5.
// d==0 -> 0.1, d=1..5 -> 0.7^d, d>5 -> 10 (FP_PEN), noTrue -> 20
__constant__ float c_tab16[16] = {
    10.0f, 0.16807f, 0.2401f, 0.343f, 0.49f, 0.7f, 0.1f, 1.0f,
    20.0f, 20.0f, 20.0f, 20.0f, 20.0f, 20.0f, 20.0f, 20.0f
};

__global__ void __launch_bounds__(BT, 2)
pal_row_kernel(const float4* __restrict__ logits4, const int* __restrict__ labels,
               float* __restrict__ out, int B)
{
    __shared__ float s_ce[512 * 17];              // padded chunk-major CE (conflict-free)
    __shared__ unsigned s_m[7][258];              // bit masks: word w at [w+1], pads at [0],[257]
    __shared__ int s_scan[NW], s_pre[NW], s_hasw[NW];
    __shared__ int s_has;
    __shared__ float s_tab[16];
    __shared__ float s_racc[NW];
    __shared__ int s_rcnt[NW], s_last;

    const int row = blockIdx.x;
    const int tid = threadIdx.x;
    const int lane = tid & 31;
    const int wid = tid >> 5;

    if (tid < 16) s_tab[tid] = c_tab16[tid];
    if (tid < 7) { s_m[tid][0] = 0; s_m[tid][257] = 0; }

    const float4* lrow = logits4 + (size_t)row * SLEN;
    const int* labrow = labels + (size_t)row * SLEN;

    // ---- Pass A: coalesced load, argmax + weighted CE -> SMEM; masks via ballot ----
#pragma unroll 4
    for (int k = 0; k < SLEN / BT; k++) {
        int i = tid + k * BT;
        float4 x = lrow[i];
        int lab = labrow[i];
        float best = x.x; int pred = 0;
        if (x.y > best) { best = x.y; pred = 1; }
        if (x.z > best) { best = x.z; pred = 2; }
        if (x.w > best) { best = x.w; pred = 3; }
        float e = __expf(x.x - best) + __expf(x.y - best) + __expf(x.z - best) + __expf(x.w - best);
        float lse = best + __logf(e);
        bool valid = ((unsigned)lab) < 4u;
        int labi = valid ? lab : 0;
        float xl = (labi == 0) ? x.x : (labi == 1) ? x.y : (labi == 2) ? x.z : x.w;
        float w = (labi >= 2) ? 30.0f : 1.0f;
        s_ce[(i >> 4) * 17 + (i & 15)] = (lse - xl) * w;

        unsigned bv  = __ballot_sync(0xffffffffu, valid);
        unsigned bt2 = __ballot_sync(0xffffffffu, lab == 2);
        unsigned bt3 = __ballot_sync(0xffffffffu, lab == 3);
        unsigned bp2 = __ballot_sync(0xffffffffu, pred == 2);
        unsigned bp3 = __ballot_sync(0xffffffffu, pred == 3);
        unsigned bpo = __ballot_sync(0xffffffffu, (pred & 1) != 0);
        unsigned blo = __ballot_sync(0xffffffffu, (lab & 1) != 0);
        if (lane == 0) {
            int wix = k * 16 + wid + 1;
            s_m[0][wix] = bv;  s_m[1][wix] = bt2; s_m[2][wix] = bt3;
            s_m[3][wix] = bp2; s_m[4][wix] = bp3; s_m[5][wix] = bpo; s_m[6][wix] = blo;
        }
    }
    __syncthreads();

    // ---- per-chunk halfword views (u16 idx: own=tid+2, prev=tid+1, next=tid+3) ----
    const unsigned short* HV  = (const unsigned short*)&s_m[0][0];
    const unsigned short* HT2 = (const unsigned short*)&s_m[1][0];
    const unsigned short* HT3 = (const unsigned short*)&s_m[2][0];
    const unsigned short* HP2 = (const unsigned short*)&s_m[3][0];
    const unsigned short* HP3 = (const unsigned short*)&s_m[4][0];
    const unsigned short* HPO = (const unsigned short*)&s_m[5][0];
    const unsigned short* HLO = (const unsigned short*)&s_m[6][0];

    unsigned hv  = HV[tid + 2];
    unsigned ht2 = HT2[tid + 2], ht2l = HT2[tid + 1], ht2r = HT2[tid + 3];
    unsigned ht3 = HT3[tid + 2], ht3l = HT3[tid + 1], ht3r = HT3[tid + 3];
    unsigned hp2 = HP2[tid + 2], hp2l = HP2[tid + 1], hp2r = HP2[tid + 3];
    unsigned hp3 = HP3[tid + 2], hp3l = HP3[tid + 1], hp3r = HP3[tid + 3];
    unsigned hpo = HPO[tid + 2];
    unsigned hlo = HLO[tid + 2];

    // ---- single block scan: carry (pred_mode, true_mode) of last valid position ----
    int vstate = -1;
    if (hv) {
        int lv = 31 - __clz(hv);
        vstate = (((tid << 4) + lv) << 2) | ((int)((hpo >> lv) & 1u) << 1) | (int)((hlo >> lv) & 1u);
    }
    int inc = vstate;
#pragma unroll
    for (int d = 1; d < 32; d <<= 1) {
        int o = __shfl_up_sync(0xffffffffu, inc, d);
        if (lane >= d) inc = max(inc, o);
    }
    int wx = __shfl_up_sync(0xffffffffu, inc, 1);
    if (lane == 0) wx = -1;
    if (lane == 31) s_scan[wid] = inc;
    int hb = (ht2 ? 1 : 0) | (ht3 ? 2 : 0) | (hp2 ? 4 : 0) | (hp3 ? 8 : 0);
    hb = __reduce_or_sync(0xffffffffu, hb);
    if (lane == 0) s_hasw[wid] = hb;
    __syncthreads();

    if (wid == 0) {
        int v = (lane < NW) ? s_scan[lane] : -1;
        int ic = v;
#pragma unroll
        for (int d = 1; d < 16; d <<= 1) {
            int o = __shfl_up_sync(0xffffffffu, ic, d);
            if (lane >= d) ic = max(ic, o);
        }
        int ex = __shfl_up_sync(0xffffffffu, ic, 1);
        if (lane == 0) ex = -1;
        if (lane < NW) s_pre[lane] = ex;
    } else if (wid == 1) {
        int v = (lane < NW) ? s_hasw[lane] : 0;
        v = __reduce_or_sync(0xffffffffu, v);
        if (lane == 0) s_has = v;
    }
    __syncthreads();

    const int pstate = max(wx, s_pre[wid]);
    const int hs = s_has;

    // ---- distance planes: windows with elements at bit 5+e, +-5 context ----
    unsigned Wt2 = (ht2l >> 11) | (ht2 << 5) | (ht2r << 21);
    unsigned Wt3 = (ht3l >> 11) | (ht3 << 5) | (ht3r << 21);
    unsigned Wp2 = (hp2l >> 11) | (hp2 << 5) | (hp2r << 21);
    unsigned Wp3 = (hp3l >> 11) | (hp3 << 5) | (hp3r << 21);
    unsigned P2e = hp2 << 5, P3e = hp3 << 5;
    unsigned T2e = ht2 << 5, T3e = ht3 << 5;

    // levels: s_k covers position iff nearest-true distance <= k (k=0..5)
    unsigned a2 = Wt2, a3 = Wt3;
    unsigned L0 = (a2 & P2e) | (a3 & P3e);
    a2 |= (a2 << 1) | (a2 >> 1); a3 |= (a3 << 1) | (a3 >> 1);
    unsigned L1 = (a2 & P2e) | (a3 & P3e);
    a2 |= (a2 << 1) | (a2 >> 1); a3 |= (a3 << 1) | (a3 >> 1);
    unsigned L2 = (a2 & P2e) | (a3 & P3e);
    a2 |= (a2 << 1) | (a2 >> 1); a3 |= (a3 << 1) | (a3 >> 1);
    unsigned L3 = (a2 & P2e) | (a3 & P3e);
    a2 |= (a2 << 1) | (a2 >> 1); a3 |= (a3 << 1) | (a3 >> 1);
    unsigned L4 = (a2 & P2e) | (a3 & P3e);
    a2 |= (a2 << 1) | (a2 >> 1); a3 |= (a3 << 1) | (a3 >> 1);
    unsigned L5 = (a2 & P2e) | (a3 & P3e);

    // bit-sliced add of 6 one-bit planes -> 3-bit levelcount planes
    unsigned x0 = L0 ^ L1 ^ L2;
    unsigned y0 = (L0 & L1) | (L2 & (L0 | L1));
    unsigned x1 = L3 ^ L4 ^ L5;
    unsigned y1 = (L3 & L4) | (L5 & (L3 | L4));
    unsigned pb0 = x0 ^ x1;
    unsigned cc = x0 & x1;
    unsigned pb1 = y0 ^ y1 ^ cc;
    unsigned pb2 = (y0 & y1) | (cc & (y0 | y1));
    unsigned pb3 = ((hs & 1) ? 0u : P2e) | ((hs & 2) ? 0u : P3e);   // no-true flag
    unsigned sel = P2e | P3e;

    // mt: radius-5 coverage of pred masks (doubling smear 1,2,2)
    unsigned cv2 = Wp2;
    cv2 |= (cv2 << 1) | (cv2 >> 1);
    cv2 |= (cv2 << 2) | (cv2 >> 2);
    cv2 |= (cv2 << 2) | (cv2 >> 2);
    unsigned cv3 = Wp3;
    cv3 |= (cv3 << 1) | (cv3 >> 1);
    cv3 |= (cv3 << 2) | (cv3 >> 2);
    cv3 |= (cv3 << 2) | (cv3 >> 2);
    unsigned mtd = ((hs & 4) ? (T2e & ~cv2) : 0u) | ((hs & 8) ? (T3e & ~cv3) : 0u); // x2.0
    unsigned mtn = ((hs & 4) ? 0u : T2e) | ((hs & 8) ? 0u : T3e);                    // x3.0

    pb0 >>= 5; pb1 >>= 5; pb2 >>= 5; pb3 >>= 5; sel >>= 5; mtd >>= 5; mtn >>= 5;

    // ---- bit-parallel sample-and-hold for mode state (bit p: p=0 seed, p=1+j elem j) ----
    int pm_in = 0, tm_in = 0;
    if (pstate >= 0) { pm_in = (pstate >> 1) & 1; tm_in = pstate & 1; }
    unsigned pres0 = (hv << 1) | 1u;
    unsigned Pm = pres0;
    unsigned Vl = ((hpo & hv) << 1) | (unsigned)pm_in;
    Vl |= (Vl << 1) & ~Pm;  Pm |= Pm << 1;
    Vl |= (Vl << 2) & ~Pm;  Pm |= Pm << 2;
    Vl |= (Vl << 4) & ~Pm;  Pm |= Pm << 4;
    Vl |= (Vl << 8) & ~Pm;  Pm |= Pm << 8;
    Vl |= (Vl << 16) & ~Pm;
    unsigned U = Vl;                       // bit e = pred_mode before element e
    Pm = pres0;
    Vl = ((hlo & hv) << 1) | (unsigned)tm_in;
    Vl |= (Vl << 1) & ~Pm;  Pm |= Pm << 1;
    Vl |= (Vl << 2) & ~Pm;  Pm |= Pm << 2;
    Vl |= (Vl << 4) & ~Pm;  Pm |= Pm << 4;
    Vl |= (Vl << 8) & ~Pm;  Pm |= Pm << 8;
    Vl |= (Vl << 16) & ~Pm;
    unsigned Ut = Vl;                      // bit e = true_mode before element e

    unsigned BAD  = ((hp2 & ~U) | (hp3 & U)) & hv;
    unsigned GOOD = ((ht2 & Ut & hp2) | (ht3 & ~Ut & hp3)) & hv;

    // ---- per-element multiply-accumulate ----
    float acc = 0.0f;
    const float* cep = s_ce + tid * 17;
#pragma unroll
    for (int e = 0; e < CH; e++) {
        unsigned idx = ((pb0 >> e) & 1u) | (((pb1 >> e) & 1u) << 1) |
                       (((pb2 >> e) & 1u) << 2) | (((pb3 >> e) & 1u) << 3);
        float m = ((sel >> e) & 1u) ? s_tab[idx] : 1.0f;
        m *= ((mtn >> e) & 1u) ? 3.0f : (((mtd >> e) & 1u) ? 2.0f : 1.0f);
        if ((BAD >> e) & 1u) m *= 100.0f;
        if ((GOOD >> e) & 1u) m *= 0.1f;
        float mv = ((hv >> e) & 1u) ? m : 0.0f;
        acc += cep[e] * mv;
    }
    int cnt = __popc(hv);

    // ---- deterministic block reduce ----
#pragma unroll
    for (int d = 16; d > 0; d >>= 1) {
        acc += __shfl_down_sync(0xffffffffu, acc, d);
        cnt += __shfl_down_sync(0xffffffffu, cnt, d);
    }
    if (lane == 0) { s_racc[wid] = acc; s_rcnt[wid] = cnt; }
    __syncthreads();
    if (wid == 0) {
        float a = (lane < NW) ? s_racc[lane] : 0.0f;
        int c = (lane < NW) ? s_rcnt[lane] : 0;
#pragma unroll
        for (int d = 8; d > 0; d >>= 1) {
            a += __shfl_down_sync(0xffffffffu, a, d);
            c += __shfl_down_sync(0xffffffffu, c, d);
        }
        if (lane == 0) {
            g_sum[row] = a; g_cnt[row] = c;
            __threadfence();
            int old = atomicAdd(&g_done, 1);
            s_last = (old == (int)gridDim.x - 1) ? 1 : 0;
        }
    }
    __syncthreads();

    // ---- last block: fixed-order final reduce (resets g_done for graph replay) ----
    if (s_last) {
        float a = 0.0f; int c = 0;
        for (int i = tid; i < B; i += BT) {
            a += __ldcg(&g_sum[i]);
            c += __ldcg(&g_cnt[i]);
        }
#pragma unroll
        for (int d = 16; d > 0; d >>= 1) {
            a += __shfl_down_sync(0xffffffffu, a, d);
            c += __shfl_down_sync(0xffffffffu, c, d);
        }
        if (lane == 0) { s_racc[wid] = a; s_rcnt[wid] = c; }
        __syncthreads();
        if (wid == 0) {
            a = (lane < NW) ? s_racc[lane] : 0.0f;
            c = (lane < NW) ? s_rcnt[lane] : 0;
#pragma unroll
            for (int d = 8; d > 0; d >>= 1) {
                a += __shfl_down_sync(0xffffffffu, a, d);
                c += __shfl_down_sync(0xffffffffu, c, d);
            }
            if (lane == 0) {
                out[0] = a / fmaxf((float)c, 1.0f);
                g_done = 0;
            }
        }
    }
}

extern "C" void kernel_launch(void* const* d_in, const int* in_sizes, int n_in,
                              void* d_out, int out_size)
{
    const float4* logits = (const float4*)d_in[0];
    const int* labels = (const int*)d_in[1];
    int B = in_sizes[1] / SLEN;
    pal_row_kernel<<<B, BT>>>(logits, labels, (float*)d_out, B);
}

// round 6
// speedup vs baseline: 3.5755x; 1.1215x over previous
#include <cuda_runtime.h>
#include <stdint.h>

#define BT 512
#define SLEN 8192
#define NW 16          // warps per block
#define NWORD 256      // 32-bit mask words per row

__device__ float g_sum[4096];
__device__ int   g_cnt[4096];
__device__ int   g_done = 0;

// idx low 4 bits: levelcount (0..6) or 7=neutral, +8 = noTrue
// levelcount = 6-d: d==0 -> 0.1, d=1..5 -> 0.7^d, d>5 -> 10, noTrue -> 20
__constant__ float c_tab16[16] = {
    10.0f, 0.16807f, 0.2401f, 0.343f, 0.49f, 0.7f, 0.1f, 1.0f,
    20.0f, 20.0f, 20.0f, 20.0f, 20.0f, 20.0f, 20.0f, 20.0f
};

__device__ __forceinline__ unsigned long long flipDiag8x8(unsigned long long x)
{
    unsigned long long t;
    t = 0x0f0f0f0f00000000ULL & (x ^ (x << 28)); x ^= t ^ (t >> 28);
    t = 0x3333000033330000ULL & (x ^ (x << 14)); x ^= t ^ (t >> 14);
    t = 0x5500550055005500ULL & (x ^ (x <<  7)); x ^= t ^ (t >>  7);
    return x;
}

__global__ void __launch_bounds__(BT, 2)
pal_row_kernel(const float4* __restrict__ logits4, const int* __restrict__ labels,
               float* __restrict__ out, int B)
{
    __shared__ float s_ce[SLEN];                     // [k*BT + tid] coalesced
    __shared__ unsigned s_m[7][NWORD + 2];           // masks, zero pads at [0],[257]
    __shared__ unsigned long long s_idx64[NWORD * 4];// per-element 8-bit multiplier idx
    __shared__ float s_tab[256];
    __shared__ int s_scan[8], s_pre[8], s_hasw[8], s_has;
    __shared__ float s_racc[NW];
    __shared__ int s_rcnt[NW], s_last;

    const int row = blockIdx.x;
    const int tid = threadIdx.x;
    const int lane = tid & 31;
    const int wid = tid >> 5;

    if (tid < 7) { s_m[tid][0] = 0; s_m[tid][NWORD + 1] = 0; }
    // threads 256..511 build the 256-entry product table
    if (tid >= NWORD) {
        int t = tid - NWORD;
        float v = c_tab16[t & 15];
        v *= ((t >> 5) & 1) ? 3.0f : (((t >> 4) & 1) ? 2.0f : 1.0f);
        if ((t >> 6) & 1) v *= 100.0f;
        if ((t >> 7) & 1) v *= 0.1f;
        s_tab[t] = v;
    }

    const float4* lrow = logits4 + (size_t)row * SLEN;
    const int* labrow = labels + (size_t)row * SLEN;

    // ---- Pass A: coalesced load, argmax + weighted CE -> SMEM; masks via ballot ----
    int cnt = 0;
#pragma unroll 4
    for (int k = 0; k < 16; k++) {
        int i = tid + k * BT;
        float4 x = lrow[i];
        int lab = labrow[i];
        float m01 = fmaxf(x.x, x.y), m23 = fmaxf(x.z, x.w);
        float best = fmaxf(m01, m23);
        bool hi = m23 > m01;
        bool b0 = hi ? (x.w > x.z) : (x.y > x.x);
        float e = __expf(x.x - best) + __expf(x.y - best) + __expf(x.z - best) + __expf(x.w - best);
        float lse = best + __logf(e);
        bool valid = (lab != -100);
        bool l0 = (lab & 1) != 0;
        bool l1 = (lab & 2) != 0;
        float xl = l1 ? (l0 ? x.w : x.z) : (l0 ? x.y : x.x);
        float ce = valid ? (lse - xl) * (l1 ? 30.0f : 1.0f) : 0.0f;
        s_ce[k * BT + tid] = ce;
        cnt += valid ? 1 : 0;
        unsigned bv  = __ballot_sync(0xffffffffu, valid);
        unsigned bt2 = __ballot_sync(0xffffffffu, lab == 2);
        unsigned bt3 = __ballot_sync(0xffffffffu, lab == 3);
        unsigned bp2 = __ballot_sync(0xffffffffu, hi && !b0);
        unsigned bp3 = __ballot_sync(0xffffffffu, hi && b0);
        unsigned bpo = __ballot_sync(0xffffffffu, b0);
        unsigned blo = __ballot_sync(0xffffffffu, l0);
        if (lane == 0) {
            int wix = k * 16 + wid + 1;
            s_m[0][wix] = bv;  s_m[1][wix] = bt2; s_m[2][wix] = bt3;
            s_m[3][wix] = bp2; s_m[4][wix] = bp3; s_m[5][wix] = bpo; s_m[6][wix] = blo;
        }
    }
    __syncthreads();

    // ---- plane phase part 1 (256 word threads): scan seeds + has flags ----
    if (tid < NWORD) {
        const int w = tid;
        unsigned hv  = s_m[0][w + 1];
        unsigned hpo = s_m[5][w + 1];
        unsigned hlo = s_m[6][w + 1];
        unsigned t2  = s_m[1][w + 1], t3 = s_m[2][w + 1];
        unsigned p2  = s_m[3][w + 1], p3 = s_m[4][w + 1];
        int vstate = -1;
        if (hv) {
            int lv = 31 - __clz(hv);
            vstate = (((w << 5) + lv) << 2) | ((int)((hpo >> lv) & 1u) << 1) | (int)((hlo >> lv) & 1u);
        }
        int inc = vstate;
#pragma unroll
        for (int d = 1; d < 32; d <<= 1) {
            int o = __shfl_up_sync(0xffffffffu, inc, d);
            if (lane >= d) inc = max(inc, o);
        }
        int wx = __shfl_up_sync(0xffffffffu, inc, 1);
        if (lane == 0) wx = -1;
        if (lane == 31) s_scan[wid] = inc;
        s_pre[0] = s_pre[0];  // no-op keep
        // stash warp-exclusive in shared? keep in reg via re-entry: store to s_idx64 scratch is overkill;
        // recompute path: we stay in the same if-block through both parts, so wx survives in a register.
        int hb = (t2 ? 1 : 0) | (t3 ? 2 : 0) | (p2 ? 4 : 0) | (p3 ? 8 : 0);
        hb = __reduce_or_sync(0xffffffffu, hb);
        if (lane == 0) s_hasw[wid] = hb;
        __syncwarp();

        // need all 8 warps' totals: block-level barrier below is outside this if,
        // so save wx and fall through after barrier; keep wx live (cheap, 1 reg).
        // (barrier happens at the __syncthreads below, all 512 threads reach it)
        //
        // -- placeholder: actual combine + part2 after the barrier --
        // store wx for re-entry
        ((int*)s_idx64)[w] = wx;   // scratch reuse, overwritten later
    }
    __syncthreads();

    if (wid == 0) {  // combine 8 warp totals
        int v = (lane < 8) ? s_scan[lane] : -1;
        int ic = v;
#pragma unroll
        for (int d = 1; d < 8; d <<= 1) {
            int o = __shfl_up_sync(0xffffffffu, ic, d);
            if (lane >= d) ic = max(ic, o);
        }
        int ex = __shfl_up_sync(0xffffffffu, ic, 1);
        if (lane == 0) ex = -1;
        if (lane < 8) s_pre[lane] = ex;
        int hw = (lane < 8) ? s_hasw[lane] : 0;
        hw = __reduce_or_sync(0xffffffffu, hw);
        if (lane == 0) s_has = hw;
    }
    __syncthreads();

    // ---- plane phase part 2 (256 word threads): distances, state, idx bytes ----
    if (tid < NWORD) {
        const int w = tid;
        const int wx = ((int*)s_idx64)[w];
        const int pstate = max(wx, s_pre[wid]);
        const int hs = s_has;

        unsigned hv  = s_m[0][w + 1];
        unsigned hpo = s_m[5][w + 1];
        unsigned hlo = s_m[6][w + 1];
        unsigned t2p = s_m[1][w], t2 = s_m[1][w + 1], t2n = s_m[1][w + 2];
        unsigned t3p = s_m[2][w], t3 = s_m[2][w + 1], t3n = s_m[2][w + 2];
        unsigned p2p = s_m[3][w], p2 = s_m[3][w + 1], p2n = s_m[3][w + 2];
        unsigned p3p = s_m[4][w], p3 = s_m[4][w + 1], p3n = s_m[4][w + 2];

        // 64-bit windows: own element e at bit 5+e, with +-5 context
        unsigned long long A2 = ((unsigned long long)(t2p >> 27)) |
                                ((unsigned long long)t2 << 5) |
                                ((unsigned long long)t2n << 37);
        unsigned long long A3 = ((unsigned long long)(t3p >> 27)) |
                                ((unsigned long long)t3 << 5) |
                                ((unsigned long long)t3n << 37);
        unsigned L0 = ((unsigned)(A2 >> 5) & p2) | ((unsigned)(A3 >> 5) & p3);
        A2 |= (A2 << 1) | (A2 >> 1);  A3 |= (A3 << 1) | (A3 >> 1);
        unsigned L1 = ((unsigned)(A2 >> 5) & p2) | ((unsigned)(A3 >> 5) & p3);
        A2 |= (A2 << 1) | (A2 >> 1);  A3 |= (A3 << 1) | (A3 >> 1);
        unsigned L2 = ((unsigned)(A2 >> 5) & p2) | ((unsigned)(A3 >> 5) & p3);
        A2 |= (A2 << 1) | (A2 >> 1);  A3 |= (A3 << 1) | (A3 >> 1);
        unsigned L3 = ((unsigned)(A2 >> 5) & p2) | ((unsigned)(A3 >> 5) & p3);
        A2 |= (A2 << 1) | (A2 >> 1);  A3 |= (A3 << 1) | (A3 >> 1);
        unsigned L4 = ((unsigned)(A2 >> 5) & p2) | ((unsigned)(A3 >> 5) & p3);
        A2 |= (A2 << 1) | (A2 >> 1);  A3 |= (A3 << 1) | (A3 >> 1);
        unsigned L5 = ((unsigned)(A2 >> 5) & p2) | ((unsigned)(A3 >> 5) & p3);

        // bit-sliced sum of 6 level planes -> 3-bit count
        unsigned x0 = L0 ^ L1 ^ L2;
        unsigned y0 = (L0 & L1) | (L2 & (L0 | L1));
        unsigned x1 = L3 ^ L4 ^ L5;
        unsigned y1 = (L3 & L4) | (L5 & (L3 | L4));
        unsigned pb0 = x0 ^ x1;
        unsigned cc = x0 & x1;
        unsigned pb1 = y0 ^ y1 ^ cc;
        unsigned pb2 = (y0 & y1) | (cc & (y0 | y1));
        unsigned sel = p2 | p3;
        unsigned pb3 = ((hs & 1) ? 0u : p2) | ((hs & 2) ? 0u : p3);

        // mt: radius-5 coverage of pred masks
        unsigned long long C2 = ((unsigned long long)(p2p >> 27)) |
                                ((unsigned long long)p2 << 5) |
                                ((unsigned long long)p2n << 37);
        unsigned long long C3 = ((unsigned long long)(p3p >> 27)) |
                                ((unsigned long long)p3 << 5) |
                                ((unsigned long long)p3n << 37);
        C2 |= (C2 << 1) | (C2 >> 1);  C2 |= (C2 << 2) | (C2 >> 2);  C2 |= (C2 << 2) | (C2 >> 2);
        C3 |= (C3 << 1) | (C3 >> 1);  C3 |= (C3 << 2) | (C3 >> 2);  C3 |= (C3 << 2) | (C3 >> 2);
        unsigned cv2 = (unsigned)(C2 >> 5), cv3 = (unsigned)(C3 >> 5);
        unsigned q4 = ((hs & 4) ? (t2 & ~cv2) : 0u) | ((hs & 8) ? (t3 & ~cv3) : 0u); // x2
        unsigned q5 = ((hs & 4) ? 0u : t2) | ((hs & 8) ? 0u : t3);                    // x3

        // bit-parallel sample-and-hold: mode state before each element
        int pm_in = 0, tm_in = 0;
        if (pstate >= 0) { pm_in = (pstate >> 1) & 1; tm_in = pstate & 1; }
        unsigned long long P0 = ((unsigned long long)hv << 1) | 1ULL;
        unsigned long long P = P0;
        unsigned long long V = ((unsigned long long)(hpo & hv) << 1) | (unsigned long long)pm_in;
        V |= (V << 1) & ~P;  P |= P << 1;
        V |= (V << 2) & ~P;  P |= P << 2;
        V |= (V << 4) & ~P;  P |= P << 4;
        V |= (V << 8) & ~P;  P |= P << 8;
        V |= (V << 16) & ~P; P |= P << 16;
        V |= (V << 32) & ~P;
        unsigned U = (unsigned)V;                 // pred_mode before element e
        P = P0;
        V = ((unsigned long long)(hlo & hv) << 1) | (unsigned long long)tm_in;
        V |= (V << 1) & ~P;  P |= P << 1;
        V |= (V << 2) & ~P;  P |= P << 2;
        V |= (V << 4) & ~P;  P |= P << 4;
        V |= (V << 8) & ~P;  P |= P << 8;
        V |= (V << 16) & ~P; P |= P << 16;
        V |= (V << 32) & ~P;
        unsigned Ut = (unsigned)V;                // true_mode before element e

        unsigned q6 = ((p2 & ~U) | (p3 & U)) & hv;                 // BAD  x100
        unsigned q7 = ((t2 & Ut & p2) | (t3 & ~Ut & p3)) & hv;     // GOOD x0.1

        unsigned q0 = pb0 | ~sel;
        unsigned q1 = pb1 | ~sel;
        unsigned q2 = pb2 | ~sel;
        unsigned q3 = pb3;

        // 8 planes -> 32 bytes: PRMT gather + 8x8 bit transpose per byte-group
#pragma unroll
        for (int g = 0; g < 4; g++) {
            unsigned s01 = (unsigned)(g | ((g + 4) << 4));
            unsigned A01 = __byte_perm(q0, q1, s01);
            unsigned A23 = __byte_perm(q2, q3, s01);
            unsigned A = __byte_perm(A01, A23, 0x5410);
            unsigned B01 = __byte_perm(q4, q5, s01);
            unsigned B23 = __byte_perm(q6, q7, s01);
            unsigned Bb = __byte_perm(B01, B23, 0x5410);
            unsigned long long xg = (unsigned long long)A | ((unsigned long long)Bb << 32);
            s_idx64[w * 4 + g] = flipDiag8x8(xg);
        }
    }
    __syncthreads();

    // ---- final MAC: coalesced, table-driven ----
    const unsigned char* s_idx = (const unsigned char*)s_idx64;
    float acc = 0.0f;
#pragma unroll
    for (int k = 0; k < 16; k++) {
        int i = tid + k * BT;
        acc += s_ce[i] * s_tab[s_idx[i]];
    }

    // ---- deterministic block reduce ----
#pragma unroll
    for (int d = 16; d > 0; d >>= 1) {
        acc += __shfl_down_sync(0xffffffffu, acc, d);
        cnt += __shfl_down_sync(0xffffffffu, cnt, d);
    }
    if (lane == 0) { s_racc[wid] = acc; s_rcnt[wid] = cnt; }
    __syncthreads();
    if (wid == 0) {
        float a = (lane < NW) ? s_racc[lane] : 0.0f;
        int c = (lane < NW) ? s_rcnt[lane] : 0;
#pragma unroll
        for (int d = 8; d > 0; d >>= 1) {
            a += __shfl_down_sync(0xffffffffu, a, d);
            c += __shfl_down_sync(0xffffffffu, c, d);
        }
        if (lane == 0) {
            g_sum[row] = a; g_cnt[row] = c;
            __threadfence();
            int old = atomicAdd(&g_done, 1);
            s_last = (old == (int)gridDim.x - 1) ? 1 : 0;
        }
    }
    __syncthreads();

    // ---- last block: fixed-order final reduce (resets g_done for graph replay) ----
    if (s_last) {
        float a = 0.0f; int c = 0;
        for (int i = tid; i < B; i += BT) {
            a += __ldcg(&g_sum[i]);
            c += __ldcg(&g_cnt[i]);
        }
#pragma unroll
        for (int d = 16; d > 0; d >>= 1) {
            a += __shfl_down_sync(0xffffffffu, a, d);
            c += __shfl_down_sync(0xffffffffu, c, d);
        }
        if (lane == 0) { s_racc[wid] = a; s_rcnt[wid] = c; }
        __syncthreads();
        if (wid == 0) {
            a = (lane < NW) ? s_racc[lane] : 0.0f;
            c = (lane < NW) ? s_rcnt[lane] : 0;
#pragma unroll
            for (int d = 8; d > 0; d >>= 1) {
                a += __shfl_down_sync(0xffffffffu, a, d);
                c += __shfl_down_sync(0xffffffffu, c, d);
            }
            if (lane == 0) {
                out[0] = a / fmaxf((float)c, 1.0f);
                g_done = 0;
            }
        }
    }
}

extern "C" void kernel_launch(void* const* d_in, const int* in_sizes, int n_in,
                              void* d_out, int out_size)
{
    const float4* logits = (const float4*)d_in[0];
    const int* labels = (const int*)d_in[1];
    int B = in_sizes[1] / SLEN;
    pal_row_kernel<<<B, BT>>>(logits, labels, (float*)d_out, B);
}

// round 11
// speedup vs baseline: 3.8283x; 1.0707x over previous
#include <cuda_runtime.h>
#include <stdint.h>

#define BT 256
#define SLEN 8192
#define NW 8           // warps per block
#define NWORD 256      // 32-bit mask words per row

__device__ float g_sum[4096];
__device__ int   g_cnt[4096];
__device__ int   g_done = 0;

// idx low 4 bits: levelcount (0..6) or 7=neutral, +8 = noTrue
// levelcount = 6-d: d==0 -> 0.1, d=1..5 -> 0.7^d, d>5 -> 10, noTrue -> 20
__constant__ float c_tab16[16] = {
    10.0f, 0.16807f, 0.2401f, 0.343f, 0.49f, 0.7f, 0.1f, 1.0f,
    20.0f, 20.0f, 20.0f, 20.0f, 20.0f, 20.0f, 20.0f, 20.0f
};

__device__ __forceinline__ unsigned long long flipDiag8x8(unsigned long long x)
{
    unsigned long long t;
    t = 0x0f0f0f0f00000000ULL & (x ^ (x << 28)); x ^= t ^ (t >> 28);
    t = 0x3333000033330000ULL & (x ^ (x << 14)); x ^= t ^ (t >> 14);
    t = 0x5500550055005500ULL & (x ^ (x <<  7)); x ^= t ^ (t >>  7);
    return x;
}

__global__ void __launch_bounds__(BT, 4)
pal_row_kernel(const float4* __restrict__ logits4, const int* __restrict__ labels,
               float* __restrict__ out, int B)
{
    __shared__ float s_ce[NWORD * 33];           // 33-stride padded: conflict-free both phases
    __shared__ unsigned s_m[7][NWORD + 2];       // masks, zero pads at [0],[257]
    __shared__ float s_tab[256];
    __shared__ int s_scan[NW], s_pre[NW], s_hasw[NW], s_has;
    __shared__ float s_racc[NW];
    __shared__ int s_rcnt[NW], s_last;

    const int row = blockIdx.x;
    const int tid = threadIdx.x;
    const int lane = tid & 31;
    const int wid = tid >> 5;

    if (tid < 7) { s_m[tid][0] = 0; s_m[tid][NWORD + 1] = 0; }
    // all 256 threads build the 256-entry product table
    {
        int t = tid;
        float v = c_tab16[t & 15];
        v *= ((t >> 5) & 1) ? 3.0f : (((t >> 4) & 1) ? 2.0f : 1.0f);
        if ((t >> 6) & 1) v *= 100.0f;
        if ((t >> 7) & 1) v *= 0.1f;
        s_tab[t] = v;
    }

    const float4* lrow = logits4 + (size_t)row * SLEN;
    const int* labrow = labels + (size_t)row * SLEN;

    // ---- Pass A: coalesced load, argmax + weighted CE -> SMEM; masks via ballot ----
#pragma unroll 4
    for (int k = 0; k < 32; k++) {
        int i = tid + (k << 8);
        float4 x = lrow[i];
        int lab = labrow[i];
        float m01 = fmaxf(x.x, x.y), m23 = fmaxf(x.z, x.w);
        float best = fmaxf(m01, m23);
        bool hi = m23 > m01;
        bool b0 = hi ? (x.w > x.z) : (x.y > x.x);
        float e = __expf(x.x - best) + __expf(x.y - best) + __expf(x.z - best) + __expf(x.w - best);
        float lse = best + __logf(e);
        bool valid = (lab != -100);
        bool l0 = (lab & 1) != 0;
        bool l1 = (lab & 2) != 0;
        float xl = l1 ? (l0 ? x.w : x.z) : (l0 ? x.y : x.x);
        float ce = valid ? (lse - xl) * (l1 ? 30.0f : 1.0f) : 0.0f;
        s_ce[(i >> 5) * 33 + (i & 31)] = ce;
        unsigned bv  = __ballot_sync(0xffffffffu, valid);
        unsigned bt2 = __ballot_sync(0xffffffffu, lab == 2);
        unsigned bt3 = __ballot_sync(0xffffffffu, lab == 3);
        unsigned bp2 = __ballot_sync(0xffffffffu, hi && !b0);
        unsigned bp3 = __ballot_sync(0xffffffffu, hi && b0);
        unsigned bpo = __ballot_sync(0xffffffffu, b0);
        unsigned blo = __ballot_sync(0xffffffffu, l0);
        if (lane == 0) {
            int wix = (k << 3) + wid + 1;
            s_m[0][wix] = bv;  s_m[1][wix] = bt2; s_m[2][wix] = bt3;
            s_m[3][wix] = bp2; s_m[4][wix] = bp3; s_m[5][wix] = bpo; s_m[6][wix] = blo;
        }
    }
    __syncthreads();

    // ---- scan seeds + has flags (each thread owns word w = tid) ----
    const int w = tid;
    unsigned hv  = s_m[0][w + 1];
    unsigned hpo = s_m[5][w + 1];
    unsigned hlo = s_m[6][w + 1];
    {
        int vstate = -1;
        if (hv) {
            int lv = 31 - __clz(hv);
            vstate = (((w << 5) + lv) << 2) | ((int)((hpo >> lv) & 1u) << 1) | (int)((hlo >> lv) & 1u);
        }
        int inc = vstate;
#pragma unroll
        for (int d = 1; d < 32; d <<= 1) {
            int o = __shfl_up_sync(0xffffffffu, inc, d);
            if (lane >= d) inc = max(inc, o);
        }
        int wx = __shfl_up_sync(0xffffffffu, inc, 1);
        if (lane == 0) wx = -1;
        if (lane == 31) s_scan[wid] = inc;
        unsigned t2w = s_m[1][w + 1], t3w = s_m[2][w + 1];
        unsigned p2w = s_m[3][w + 1], p3w = s_m[4][w + 1];
        int hb = (t2w ? 1 : 0) | (t3w ? 2 : 0) | (p2w ? 4 : 0) | (p3w ? 8 : 0);
        hb = __reduce_or_sync(0xffffffffu, hb);
        if (lane == 0) s_hasw[wid] = hb;
        __syncthreads();

        if (wid == 0) {  // combine 8 warp totals
            int v = (lane < NW) ? s_scan[lane] : -1;
            int ic = v;
#pragma unroll
            for (int d = 1; d < NW; d <<= 1) {
                int o = __shfl_up_sync(0xffffffffu, ic, d);
                if (lane >= d) ic = max(ic, o);
            }
            int ex = __shfl_up_sync(0xffffffffu, ic, 1);
            if (lane == 0) ex = -1;
            if (lane < NW) s_pre[lane] = ex;
            int hw = (lane < NW) ? s_hasw[lane] : 0;
            hw = __reduce_or_sync(0xffffffffu, hw);
            if (lane == 0) s_has = hw;
        }
        __syncthreads();

        const int pstate = max(wx, s_pre[wid]);
        const int hs = s_has;

        // ---- planes: distances, mode state, per-element idx -> fused MAC ----
        unsigned t2p = s_m[1][w], t2 = s_m[1][w + 1], t2n = s_m[1][w + 2];
        unsigned t3p = s_m[2][w], t3 = s_m[2][w + 1], t3n = s_m[2][w + 2];
        unsigned p2p = s_m[3][w], p2 = s_m[3][w + 1], p2n = s_m[3][w + 2];
        unsigned p3p = s_m[4][w], p3 = s_m[4][w + 1], p3n = s_m[4][w + 2];

        // 64-bit windows: own element e at bit 5+e, with +-5 context
        unsigned long long A2 = ((unsigned long long)(t2p >> 27)) |
                                ((unsigned long long)t2 << 5) |
                                ((unsigned long long)t2n << 37);
        unsigned long long A3 = ((unsigned long long)(t3p >> 27)) |
                                ((unsigned long long)t3 << 5) |
                                ((unsigned long long)t3n << 37);
        unsigned L0 = ((unsigned)(A2 >> 5) & p2) | ((unsigned)(A3 >> 5) & p3);
        A2 |= (A2 << 1) | (A2 >> 1);  A3 |= (A3 << 1) | (A3 >> 1);
        unsigned L1 = ((unsigned)(A2 >> 5) & p2) | ((unsigned)(A3 >> 5) & p3);
        A2 |= (A2 << 1) | (A2 >> 1);  A3 |= (A3 << 1) | (A3 >> 1);
        unsigned L2 = ((unsigned)(A2 >> 5) & p2) | ((unsigned)(A3 >> 5) & p3);
        A2 |= (A2 << 1) | (A2 >> 1);  A3 |= (A3 << 1) | (A3 >> 1);
        unsigned L3 = ((unsigned)(A2 >> 5) & p2) | ((unsigned)(A3 >> 5) & p3);
        A2 |= (A2 << 1) | (A2 >> 1);  A3 |= (A3 << 1) | (A3 >> 1);
        unsigned L4 = ((unsigned)(A2 >> 5) & p2) | ((unsigned)(A3 >> 5) & p3);
        A2 |= (A2 << 1) | (A2 >> 1);  A3 |= (A3 << 1) | (A3 >> 1);
        unsigned L5 = ((unsigned)(A2 >> 5) & p2) | ((unsigned)(A3 >> 5) & p3);

        // bit-sliced sum of 6 level planes -> 3-bit count
        unsigned x0 = L0 ^ L1 ^ L2;
        unsigned y0 = (L0 & L1) | (L2 & (L0 | L1));
        unsigned x1 = L3 ^ L4 ^ L5;
        unsigned y1 = (L3 & L4) | (L5 & (L3 | L4));
        unsigned pb0 = x0 ^ x1;
        unsigned cc = x0 & x1;
        unsigned pb1 = y0 ^ y1 ^ cc;
        unsigned pb2 = (y0 & y1) | (cc & (y0 | y1));
        unsigned sel = p2 | p3;
        unsigned pb3 = ((hs & 1) ? 0u : p2) | ((hs & 2) ? 0u : p3);

        // mt: radius-5 coverage of pred masks
        unsigned long long C2 = ((unsigned long long)(p2p >> 27)) |
                                ((unsigned long long)p2 << 5) |
                                ((unsigned long long)p2n << 37);
        unsigned long long C3 = ((unsigned long long)(p3p >> 27)) |
                                ((unsigned long long)p3 << 5) |
                                ((unsigned long long)p3n << 37);
        C2 |= (C2 << 1) | (C2 >> 1);  C2 |= (C2 << 2) | (C2 >> 2);  C2 |= (C2 << 2) | (C2 >> 2);
        C3 |= (C3 << 1) | (C3 >> 1);  C3 |= (C3 << 2) | (C3 >> 2);  C3 |= (C3 << 2) | (C3 >> 2);
        unsigned cv2 = (unsigned)(C2 >> 5), cv3 = (unsigned)(C3 >> 5);
        unsigned q4 = ((hs & 4) ? (t2 & ~cv2) : 0u) | ((hs & 8) ? (t3 & ~cv3) : 0u); // x2
        unsigned q5 = ((hs & 4) ? 0u : t2) | ((hs & 8) ? 0u : t3);                    // x3

        // bit-parallel sample-and-hold: mode state before each element
        int pm_in = 0, tm_in = 0;
        if (pstate >= 0) { pm_in = (pstate >> 1) & 1; tm_in = pstate & 1; }
        unsigned long long P0 = ((unsigned long long)hv << 1) | 1ULL;
        unsigned long long P = P0;
        unsigned long long V = ((unsigned long long)(hpo & hv) << 1) | (unsigned long long)pm_in;
        V |= (V << 1) & ~P;  P |= P << 1;
        V |= (V << 2) & ~P;  P |= P << 2;
        V |= (V << 4) & ~P;  P |= P << 4;
        V |= (V << 8) & ~P;  P |= P << 8;
        V |= (V << 16) & ~P; P |= P << 16;
        V |= (V << 32) & ~P;
        unsigned U = (unsigned)V;                 // pred_mode before element e
        P = P0;
        V = ((unsigned long long)(hlo & hv) << 1) | (unsigned long long)tm_in;
        V |= (V << 1) & ~P;  P |= P << 1;
        V |= (V << 2) & ~P;  P |= P << 2;
        V |= (V << 4) & ~P;  P |= P << 4;
        V |= (V << 8) & ~P;  P |= P << 8;
        V |= (V << 16) & ~P; P |= P << 16;
        V |= (V << 32) & ~P;
        unsigned Ut = (unsigned)V;                // true_mode before element e

        unsigned q6 = ((p2 & ~U) | (p3 & U)) & hv;                 // BAD  x100
        unsigned q7 = ((t2 & Ut & p2) | (t3 & ~Ut & p3)) & hv;     // GOOD x0.1

        unsigned q0 = pb0 | ~sel;
        unsigned q1 = pb1 | ~sel;
        unsigned q2 = pb2 | ~sel;
        unsigned q3 = pb3;

        // fused MAC: transpose 8 planes -> idx bytes in regs, gather table, FMA
        float acc = 0.0f;
        const float* cep = s_ce + w * 33;
#pragma unroll
        for (int g = 0; g < 4; g++) {
            unsigned s01 = (unsigned)(g | ((g + 4) << 4));
            unsigned A01 = __byte_perm(q0, q1, s01);
            unsigned A23 = __byte_perm(q2, q3, s01);
            unsigned Aw = __byte_perm(A01, A23, 0x5410);
            unsigned B01 = __byte_perm(q4, q5, s01);
            unsigned B23 = __byte_perm(q6, q7, s01);
            unsigned Bw = __byte_perm(B01, B23, 0x5410);
            unsigned long long tg = flipDiag8x8((unsigned long long)Aw | ((unsigned long long)Bw << 32));
            unsigned lo = (unsigned)tg, hi32 = (unsigned)(tg >> 32);
#pragma unroll
            for (int b = 0; b < 4; b++)
                acc += cep[g * 8 + b] * s_tab[(lo >> (8 * b)) & 0xffu];
#pragma unroll
            for (int b = 0; b < 4; b++)
                acc += cep[g * 8 + 4 + b] * s_tab[(hi32 >> (8 * b)) & 0xffu];
        }
        int cnt = __popc(hv);

        // ---- deterministic block reduce ----
#pragma unroll
        for (int d = 16; d > 0; d >>= 1) {
            acc += __shfl_down_sync(0xffffffffu, acc, d);
            cnt += __shfl_down_sync(0xffffffffu, cnt, d);
        }
        if (lane == 0) { s_racc[wid] = acc; s_rcnt[wid] = cnt; }
    }
    __syncthreads();
    if (wid == 0) {
        float a = (lane < NW) ? s_racc[lane] : 0.0f;
        int c = (lane < NW) ? s_rcnt[lane] : 0;
#pragma unroll
        for (int d = 4; d > 0; d >>= 1) {
            a += __shfl_down_sync(0xffffffffu, a, d);
            c += __shfl_down_sync(0xffffffffu, c, d);
        }
        if (lane == 0) {
            g_sum[row] = a; g_cnt[row] = c;
            __threadfence();
            int old = atomicAdd(&g_done, 1);
            s_last = (old == (int)gridDim.x - 1) ? 1 : 0;
        }
    }
    __syncthreads();

    // ---- last block: fixed-order final reduce (resets g_done for graph replay) ----
    if (s_last) {
        float a = 0.0f; int c = 0;
        for (int i = tid; i < B; i += BT) {
            a += __ldcg(&g_sum[i]);
            c += __ldcg(&g_cnt[i]);
        }
#pragma unroll
        for (int d = 16; d > 0; d >>= 1) {
            a += __shfl_down_sync(0xffffffffu, a, d);
            c += __shfl_down_sync(0xffffffffu, c, d);
        }
        if (lane == 0) { s_racc[wid] = a; s_rcnt[wid] = c; }
        __syncthreads();
        if (wid == 0) {
            a = (lane < NW) ? s_racc[lane] : 0.0f;
            c = (lane < NW) ? s_rcnt[lane] : 0;
#pragma unroll
            for (int d = 4; d > 0; d >>= 1) {
                a += __shfl_down_sync(0xffffffffu, a, d);
                c += __shfl_down_sync(0xffffffffu, c, d);
            }
            if (lane == 0) {
                out[0] = a / fmaxf((float)c, 1.0f);
                g_done = 0;
            }
        }
    }
}

extern "C" void kernel_launch(void* const* d_in, const int* in_sizes, int n_in,
                              void* d_out, int out_size)
{
    const float4* logits = (const float4*)d_in[0];
    const int* labels = (const int*)d_in[1];
    int B = in_sizes[1] / SLEN;
    pal_row_kernel<<<B, BT>>>(logits, labels, (float*)d_out, B);
}

// round 12
// speedup vs baseline: 3.8723x; 1.0115x over previous
#include <cuda_runtime.h>
#include <stdint.h>

#define BT 256
#define SLEN 8192
#define NW 8           // warps per block
#define NWORD 256      // 32-bit mask words per row

__device__ float g_sum[4096];
__device__ int   g_cnt[4096];
__device__ int   g_done = 0;

// idx low 4 bits: levelcount (0..6) or 7=neutral, +8 = noTrue
// levelcount = 6-d: d==0 -> 0.1, d=1..5 -> 0.7^d, d>5 -> 10, noTrue -> 20
__constant__ float c_tab16[16] = {
    10.0f, 0.16807f, 0.2401f, 0.343f, 0.49f, 0.7f, 0.1f, 1.0f,
    20.0f, 20.0f, 20.0f, 20.0f, 20.0f, 20.0f, 20.0f, 20.0f
};

__device__ __forceinline__ unsigned long long flipDiag8x8(unsigned long long x)
{
    unsigned long long t;
    t = 0x0f0f0f0f00000000ULL & (x ^ (x << 28)); x ^= t ^ (t >> 28);
    t = 0x3333000033330000ULL & (x ^ (x << 14)); x ^= t ^ (t >> 14);
    t = 0x5500550055005500ULL & (x ^ (x <<  7)); x ^= t ^ (t >>  7);
    return x;
}

__global__ void __launch_bounds__(BT, 4)
pal_row_kernel(const float4* __restrict__ logits4, const int* __restrict__ labels,
               float* __restrict__ out, int B)
{
    __shared__ float s_ce[NWORD * 33];           // 33-stride padded: conflict-free both phases
    __shared__ unsigned s_m[5][NWORD + 2];       // valid,l0,l1,hi,podd; zero pads at [0],[257]
    __shared__ float s_tab[256];
    __shared__ int s_scan[NW], s_hasw[NW];
    __shared__ float s_racc[NW];
    __shared__ int s_rcnt[NW], s_last;

    const int row = blockIdx.x;
    const int tid = threadIdx.x;
    const int lane = tid & 31;
    const int wid = tid >> 5;

    if (tid < 5) { s_m[tid][0] = 0; s_m[tid][NWORD + 1] = 0; }
    // all 256 threads build the 256-entry product table
    {
        int t = tid;
        float v = c_tab16[t & 15];
        v *= ((t >> 5) & 1) ? 3.0f : (((t >> 4) & 1) ? 2.0f : 1.0f);
        if ((t >> 6) & 1) v *= 100.0f;
        if ((t >> 7) & 1) v *= 0.1f;
        s_tab[t] = v;
    }

    const float4* lrow = logits4 + (size_t)row * SLEN;
    const int* labrow = labels + (size_t)row * SLEN;

    // ---- Pass A: 2 elements/thread/iter, full unroll; 5 ballots per 32 elems ----
#pragma unroll
    for (int k = 0; k < 16; k++) {
        const int i0 = tid + (k << 8);
        const int i1 = i0 + 4096;
        float4 xa = __ldcs(lrow + i0);
        float4 xb = __ldcs(lrow + i1);
        int la = __ldcs(labrow + i0);
        int lb = __ldcs(labrow + i1);

        // element a
        float am01 = fmaxf(xa.x, xa.y), am23 = fmaxf(xa.z, xa.w);
        float abest = fmaxf(am01, am23);
        bool ahi = am23 > am01;
        bool ab0 = ahi ? (xa.w > xa.z) : (xa.y > xa.x);
        float ae = __expf(xa.x - abest) + __expf(xa.y - abest) +
                   __expf(xa.z - abest) + __expf(xa.w - abest);
        float alse = abest + __logf(ae);
        bool avalid = (la != -100);
        bool al0 = (la & 1) != 0;
        bool al1 = (la & 2) != 0;
        float axl = al1 ? (al0 ? xa.w : xa.z) : (al0 ? xa.y : xa.x);
        float ace = avalid ? (alse - axl) * (al1 ? 30.0f : 1.0f) : 0.0f;
        s_ce[(i0 >> 5) * 33 + (i0 & 31)] = ace;

        // element b
        float bm01 = fmaxf(xb.x, xb.y), bm23 = fmaxf(xb.z, xb.w);
        float bbest = fmaxf(bm01, bm23);
        bool bhi = bm23 > bm01;
        bool bb0 = bhi ? (xb.w > xb.z) : (xb.y > xb.x);
        float be = __expf(xb.x - bbest) + __expf(xb.y - bbest) +
                   __expf(xb.z - bbest) + __expf(xb.w - bbest);
        float blse = bbest + __logf(be);
        bool bvalid = (lb != -100);
        bool bl0 = (lb & 1) != 0;
        bool bl1 = (lb & 2) != 0;
        float bxl = bl1 ? (bl0 ? xb.w : xb.z) : (bl0 ? xb.y : xb.x);
        float bce = bvalid ? (blse - bxl) * (bl1 ? 30.0f : 1.0f) : 0.0f;
        s_ce[(i1 >> 5) * 33 + (i1 & 31)] = bce;

        unsigned av  = __ballot_sync(0xffffffffu, avalid);
        unsigned aL0 = __ballot_sync(0xffffffffu, al0);
        unsigned aL1 = __ballot_sync(0xffffffffu, al1);
        unsigned aHI = __ballot_sync(0xffffffffu, ahi);
        unsigned aPO = __ballot_sync(0xffffffffu, ab0);
        unsigned bv  = __ballot_sync(0xffffffffu, bvalid);
        unsigned bL0 = __ballot_sync(0xffffffffu, bl0);
        unsigned bL1 = __ballot_sync(0xffffffffu, bl1);
        unsigned bHI = __ballot_sync(0xffffffffu, bhi);
        unsigned bPO = __ballot_sync(0xffffffffu, bb0);
        if (lane == 0) {
            int wa = (k << 3) + wid + 1;
            int wb = wa + 128;
            s_m[0][wa] = av;  s_m[1][wa] = aL0; s_m[2][wa] = aL1;
            s_m[3][wa] = aHI; s_m[4][wa] = aPO;
            s_m[0][wb] = bv;  s_m[1][wb] = bL0; s_m[2][wb] = bL1;
            s_m[3][wb] = bHI; s_m[4][wb] = bPO;
        }
    }
    __syncthreads();

    // ---- each thread owns word w = tid ----
    const int w = tid;
    unsigned hv  = s_m[0][w + 1];
    unsigned hlo = s_m[1][w + 1];
    unsigned hl1 = s_m[2][w + 1];
    unsigned hhi = s_m[3][w + 1];
    unsigned hpo = s_m[4][w + 1];
    unsigned t2 = hl1 & ~hlo, t3 = hl1 & hlo;
    unsigned p2 = hhi & ~hpo, p3 = hhi & hpo;
    {
        // scan seed: last valid position's (pred_mode, true_mode)
        int vstate = -1;
        if (hv) {
            int lv = 31 - __clz(hv);
            vstate = (((w << 5) + lv) << 2) | ((int)((hpo >> lv) & 1u) << 1) | (int)((hlo >> lv) & 1u);
        }
        int inc = vstate;
#pragma unroll
        for (int d = 1; d < 32; d <<= 1) {
            int o = __shfl_up_sync(0xffffffffu, inc, d);
            if (lane >= d) inc = max(inc, o);
        }
        int wx = __shfl_up_sync(0xffffffffu, inc, 1);
        if (lane == 0) wx = -1;
        if (lane == 31) s_scan[wid] = inc;
        int hb = (t2 ? 1 : 0) | (t3 ? 2 : 0) | (p2 ? 4 : 0) | (p3 ? 8 : 0);
        hb = __reduce_or_sync(0xffffffffu, hb);
        if (lane == 0) s_hasw[wid] = hb;
        __syncthreads();

        // all threads combine the 8 warp totals serially (8 entries)
        int wpre = -1, hs = 0;
#pragma unroll
        for (int ww = 0; ww < NW; ww++) {
            int t = s_scan[ww];
            if (ww < wid) wpre = max(wpre, t);
            hs |= s_hasw[ww];
        }
        const int pstate = max(wx, wpre);

        // ---- planes: distances, mode state, per-element idx -> fused MAC ----
        unsigned l0p = s_m[1][w], l0n = s_m[1][w + 2];
        unsigned l1p = s_m[2][w], l1n = s_m[2][w + 2];
        unsigned hip = s_m[3][w], hin = s_m[3][w + 2];
        unsigned pop = s_m[4][w], pon = s_m[4][w + 2];
        unsigned t2p = l1p & ~l0p, t2n = l1n & ~l0n;
        unsigned t3p = l1p & l0p,  t3n = l1n & l0n;
        unsigned p2p = hip & ~pop, p2n = hin & ~pon;
        unsigned p3p = hip & pop,  p3n = hin & pon;

        // 64-bit windows: own element e at bit 5+e, with +-5 context
        unsigned long long A2 = ((unsigned long long)(t2p >> 27)) |
                                ((unsigned long long)t2 << 5) |
                                ((unsigned long long)t2n << 37);
        unsigned long long A3 = ((unsigned long long)(t3p >> 27)) |
                                ((unsigned long long)t3 << 5) |
                                ((unsigned long long)t3n << 37);
        unsigned L0 = ((unsigned)(A2 >> 5) & p2) | ((unsigned)(A3 >> 5) & p3);
        A2 |= (A2 << 1) | (A2 >> 1);  A3 |= (A3 << 1) | (A3 >> 1);
        unsigned L1 = ((unsigned)(A2 >> 5) & p2) | ((unsigned)(A3 >> 5) & p3);
        A2 |= (A2 << 1) | (A2 >> 1);  A3 |= (A3 << 1) | (A3 >> 1);
        unsigned L2 = ((unsigned)(A2 >> 5) & p2) | ((unsigned)(A3 >> 5) & p3);
        A2 |= (A2 << 1) | (A2 >> 1);  A3 |= (A3 << 1) | (A3 >> 1);
        unsigned L3 = ((unsigned)(A2 >> 5) & p2) | ((unsigned)(A3 >> 5) & p3);
        A2 |= (A2 << 1) | (A2 >> 1);  A3 |= (A3 << 1) | (A3 >> 1);
        unsigned L4 = ((unsigned)(A2 >> 5) & p2) | ((unsigned)(A3 >> 5) & p3);
        A2 |= (A2 << 1) | (A2 >> 1);  A3 |= (A3 << 1) | (A3 >> 1);
        unsigned L5 = ((unsigned)(A2 >> 5) & p2) | ((unsigned)(A3 >> 5) & p3);

        // bit-sliced sum of 6 level planes -> 3-bit count
        unsigned x0 = L0 ^ L1 ^ L2;
        unsigned y0 = (L0 & L1) | (L2 & (L0 | L1));
        unsigned x1 = L3 ^ L4 ^ L5;
        unsigned y1 = (L3 & L4) | (L5 & (L3 | L4));
        unsigned pb0 = x0 ^ x1;
        unsigned cc = x0 & x1;
        unsigned pb1 = y0 ^ y1 ^ cc;
        unsigned pb2 = (y0 & y1) | (cc & (y0 | y1));
        unsigned sel = p2 | p3;
        unsigned pb3 = ((hs & 1) ? 0u : p2) | ((hs & 2) ? 0u : p3);

        // mt: radius-5 coverage of pred masks
        unsigned long long C2 = ((unsigned long long)(p2p >> 27)) |
                                ((unsigned long long)p2 << 5) |
                                ((unsigned long long)p2n << 37);
        unsigned long long C3 = ((unsigned long long)(p3p >> 27)) |
                                ((unsigned long long)p3 << 5) |
                                ((unsigned long long)p3n << 37);
        C2 |= (C2 << 1) | (C2 >> 1);  C2 |= (C2 << 2) | (C2 >> 2);  C2 |= (C2 << 2) | (C2 >> 2);
        C3 |= (C3 << 1) | (C3 >> 1);  C3 |= (C3 << 2) | (C3 >> 2);  C3 |= (C3 << 2) | (C3 >> 2);
        unsigned cv2 = (unsigned)(C2 >> 5), cv3 = (unsigned)(C3 >> 5);
        unsigned q4 = ((hs & 4) ? (t2 & ~cv2) : 0u) | ((hs & 8) ? (t3 & ~cv3) : 0u); // x2
        unsigned q5 = ((hs & 4) ? 0u : t2) | ((hs & 8) ? 0u : t3);                    // x3

        // bit-parallel sample-and-hold: mode state before each element
        int pm_in = 0, tm_in = 0;
        if (pstate >= 0) { pm_in = (pstate >> 1) & 1; tm_in = pstate & 1; }
        unsigned long long P0 = ((unsigned long long)hv << 1) | 1ULL;
        unsigned long long P = P0;
        unsigned long long V = ((unsigned long long)(hpo & hv) << 1) | (unsigned long long)pm_in;
        V |= (V << 1) & ~P;  P |= P << 1;
        V |= (V << 2) & ~P;  P |= P << 2;
        V |= (V << 4) & ~P;  P |= P << 4;
        V |= (V << 8) & ~P;  P |= P << 8;
        V |= (V << 16) & ~P; P |= P << 16;
        V |= (V << 32) & ~P;
        unsigned U = (unsigned)V;                 // pred_mode before element e
        P = P0;
        V = ((unsigned long long)(hlo & hv) << 1) | (unsigned long long)tm_in;
        V |= (V << 1) & ~P;  P |= P << 1;
        V |= (V << 2) & ~P;  P |= P << 2;
        V |= (V << 4) & ~P;  P |= P << 4;
        V |= (V << 8) & ~P;  P |= P << 8;
        V |= (V << 16) & ~P; P |= P << 16;
        V |= (V << 32) & ~P;
        unsigned Ut = (unsigned)V;                // true_mode before element e

        unsigned q6 = ((p2 & ~U) | (p3 & U)) & hv;                 // BAD  x100
        unsigned q7 = ((t2 & Ut & p2) | (t3 & ~Ut & p3)) & hv;     // GOOD x0.1

        unsigned q0 = pb0 | ~sel;
        unsigned q1 = pb1 | ~sel;
        unsigned q2 = pb2 | ~sel;
        unsigned q3 = pb3;

        // fused MAC: transpose 8 planes -> idx bytes in regs, gather table, FMA
        float acc = 0.0f;
        const float* cep = s_ce + w * 33;
#pragma unroll
        for (int g = 0; g < 4; g++) {
            unsigned s01 = (unsigned)(g | ((g + 4) << 4));
            unsigned A01 = __byte_perm(q0, q1, s01);
            unsigned A23 = __byte_perm(q2, q3, s01);
            unsigned Aw = __byte_perm(A01, A23, 0x5410);
            unsigned B01 = __byte_perm(q4, q5, s01);
            unsigned B23 = __byte_perm(q6, q7, s01);
            unsigned Bw = __byte_perm(B01, B23, 0x5410);
            unsigned long long tg = flipDiag8x8((unsigned long long)Aw | ((unsigned long long)Bw << 32));
            unsigned lo = (unsigned)tg, hi32 = (unsigned)(tg >> 32);
#pragma unroll
            for (int b = 0; b < 4; b++)
                acc += cep[g * 8 + b] * s_tab[(lo >> (8 * b)) & 0xffu];
#pragma unroll
            for (int b = 0; b < 4; b++)
                acc += cep[g * 8 + 4 + b] * s_tab[(hi32 >> (8 * b)) & 0xffu];
        }
        int cnt = __popc(hv);

        // ---- deterministic block reduce ----
#pragma unroll
        for (int d = 16; d > 0; d >>= 1) {
            acc += __shfl_down_sync(0xffffffffu, acc, d);
            cnt += __shfl_down_sync(0xffffffffu, cnt, d);
        }
        if (lane == 0) { s_racc[wid] = acc; s_rcnt[wid] = cnt; }
    }
    __syncthreads();
    if (wid == 0) {
        float a = (lane < NW) ? s_racc[lane] : 0.0f;
        int c = (lane < NW) ? s_rcnt[lane] : 0;
#pragma unroll
        for (int d = 4; d > 0; d >>= 1) {
            a += __shfl_down_sync(0xffffffffu, a, d);
            c += __shfl_down_sync(0xffffffffu, c, d);
        }
        if (lane == 0) {
            g_sum[row] = a; g_cnt[row] = c;
            __threadfence();
            int old = atomicAdd(&g_done, 1);
            s_last = (old == (int)gridDim.x - 1) ? 1 : 0;
        }
    }
    __syncthreads();

    // ---- last block: fixed-order final reduce (resets g_done for graph replay) ----
    if (s_last) {
        float a = 0.0f; int c = 0;
        for (int i = tid; i < B; i += BT) {
            a += __ldcg(&g_sum[i]);
            c += __ldcg(&g_cnt[i]);
        }
#pragma unroll
        for (int d = 16; d > 0; d >>= 1) {
            a += __shfl_down_sync(0xffffffffu, a, d);
            c += __shfl_down_sync(0xffffffffu, c, d);
        }
        if (lane == 0) { s_racc[wid] = a; s_rcnt[wid] = c; }
        __syncthreads();
        if (wid == 0) {
            a = (lane < NW) ? s_racc[lane] : 0.0f;
            c = (lane < NW) ? s_rcnt[lane] : 0;
#pragma unroll
            for (int d = 4; d > 0; d >>= 1) {
                a += __shfl_down_sync(0xffffffffu, a, d);
                c += __shfl_down_sync(0xffffffffu, c, d);
            }
            if (lane == 0) {
                out[0] = a / fmaxf((float)c, 1.0f);
                g_done = 0;
            }
        }
    }
}

extern "C" void kernel_launch(void* const* d_in, const int* in_sizes, int n_in,
                              void* d_out, int out_size)
{
    const float4* logits = (const float4*)d_in[0];
    const int* labels = (const int*)d_in[1];
    int B = in_sizes[1] / SLEN;
    pal_row_kernel<<<B, BT>>>(logits, labels, (float*)d_out, B);
}

// round 13
// speedup vs baseline: 3.9275x; 1.0142x over previous
#include <cuda_runtime.h>
#include <stdint.h>

#define BT 256
#define SLEN 8192
#define NW 8           // warps per block
#define NWORD 256      // 32-bit mask words per row

__device__ float g_sum[4096];
__device__ int   g_cnt[4096];
__device__ int   g_done = 0;

// idx low 4 bits: levelcount (0..6) or 7=neutral, +8 = noTrue
// levelcount = 6-d: d==0 -> 0.1, d=1..5 -> 0.7^d, d>5 -> 10, noTrue -> 20
__constant__ float c_tab16[16] = {
    10.0f, 0.16807f, 0.2401f, 0.343f, 0.49f, 0.7f, 0.1f, 1.0f,
    20.0f, 20.0f, 20.0f, 20.0f, 20.0f, 20.0f, 20.0f, 20.0f
};

__device__ __forceinline__ unsigned long long flipDiag8x8(unsigned long long x)
{
    unsigned long long t;
    t = 0x0f0f0f0f00000000ULL & (x ^ (x << 28)); x ^= t ^ (t >> 28);
    t = 0x3333000033330000ULL & (x ^ (x << 14)); x ^= t ^ (t >> 14);
    t = 0x5500550055005500ULL & (x ^ (x <<  7)); x ^= t ^ (t >>  7);
    return x;
}

__global__ void __launch_bounds__(BT, 5)
pal_row_kernel(const float4* __restrict__ logits4, const int* __restrict__ labels,
               float* __restrict__ out, int B)
{
    __shared__ float s_ce[NWORD * 33];           // 33-stride padded: conflict-free both phases
    __shared__ unsigned s_m[5][NWORD + 2];       // valid,l0,l1,hi,podd; zero pads at [0],[257]
    __shared__ float s_tab[256];
    __shared__ int s_scan[NW], s_hasw[NW];
    __shared__ float s_racc[NW];
    __shared__ int s_rcnt[NW], s_last;

    const int row = blockIdx.x;
    const int tid = threadIdx.x;
    const int lane = tid & 31;
    const int wid = tid >> 5;

    if (tid < 5) { s_m[tid][0] = 0; s_m[tid][NWORD + 1] = 0; }
    // all 256 threads build the 256-entry product table
    {
        int t = tid;
        float v = c_tab16[t & 15];
        v *= ((t >> 5) & 1) ? 3.0f : (((t >> 4) & 1) ? 2.0f : 1.0f);
        if ((t >> 6) & 1) v *= 100.0f;
        if ((t >> 7) & 1) v *= 0.1f;
        s_tab[t] = v;
    }

    const float4* lrow = logits4 + (size_t)row * SLEN;
    const int* labrow = labels + (size_t)row * SLEN;

    // ---- Pass A: 2 elements/thread/iter, full unroll; 5 ballots per 32 elems ----
#pragma unroll
    for (int k = 0; k < 16; k++) {
        const int i0 = tid + (k << 8);
        const int i1 = i0 + 4096;
        float4 xa = __ldcs(lrow + i0);
        float4 xb = __ldcs(lrow + i1);
        int la = __ldcs(labrow + i0);
        int lb = __ldcs(labrow + i1);

        // element a
        float am01 = fmaxf(xa.x, xa.y), am23 = fmaxf(xa.z, xa.w);
        float abest = fmaxf(am01, am23);
        bool ahi = am23 > am01;
        bool ab0 = ahi ? (xa.w > xa.z) : (xa.y > xa.x);
        float ae = __expf(xa.x - abest) + __expf(xa.y - abest) +
                   __expf(xa.z - abest) + __expf(xa.w - abest);
        float alse = abest + __logf(ae);
        bool avalid = (la != -100);
        bool al0 = (la & 1) != 0;
        bool al1 = (la & 2) != 0;
        float axl = al1 ? (al0 ? xa.w : xa.z) : (al0 ? xa.y : xa.x);
        float ace = avalid ? (alse - axl) * (al1 ? 30.0f : 1.0f) : 0.0f;
        s_ce[(i0 >> 5) * 33 + (i0 & 31)] = ace;

        // element b
        float bm01 = fmaxf(xb.x, xb.y), bm23 = fmaxf(xb.z, xb.w);
        float bbest = fmaxf(bm01, bm23);
        bool bhi = bm23 > bm01;
        bool bb0 = bhi ? (xb.w > xb.z) : (xb.y > xb.x);
        float be = __expf(xb.x - bbest) + __expf(xb.y - bbest) +
                   __expf(xb.z - bbest) + __expf(xb.w - bbest);
        float blse = bbest + __logf(be);
        bool bvalid = (lb != -100);
        bool bl0 = (lb & 1) != 0;
        bool bl1 = (lb & 2) != 0;
        float bxl = bl1 ? (bl0 ? xb.w : xb.z) : (bl0 ? xb.y : xb.x);
        float bce = bvalid ? (blse - bxl) * (bl1 ? 30.0f : 1.0f) : 0.0f;
        s_ce[(i1 >> 5) * 33 + (i1 & 31)] = bce;

        unsigned av  = __ballot_sync(0xffffffffu, avalid);
        unsigned aL0 = __ballot_sync(0xffffffffu, al0);
        unsigned aL1 = __ballot_sync(0xffffffffu, al1);
        unsigned aHI = __ballot_sync(0xffffffffu, ahi);
        unsigned aPO = __ballot_sync(0xffffffffu, ab0);
        unsigned bv  = __ballot_sync(0xffffffffu, bvalid);
        unsigned bL0 = __ballot_sync(0xffffffffu, bl0);
        unsigned bL1 = __ballot_sync(0xffffffffu, bl1);
        unsigned bHI = __ballot_sync(0xffffffffu, bhi);
        unsigned bPO = __ballot_sync(0xffffffffu, bb0);
        if (lane == 0) {
            int wa = (k << 3) + wid + 1;
            int wb = wa + 128;
            s_m[0][wa] = av;  s_m[1][wa] = aL0; s_m[2][wa] = aL1;
            s_m[3][wa] = aHI; s_m[4][wa] = aPO;
            s_m[0][wb] = bv;  s_m[1][wb] = bL0; s_m[2][wb] = bL1;
            s_m[3][wb] = bHI; s_m[4][wb] = bPO;
        }
    }
    __syncthreads();

    // ---- each thread owns word w = tid ----
    const int w = tid;
    unsigned hv  = s_m[0][w + 1];
    unsigned hlo = s_m[1][w + 1];
    unsigned hl1 = s_m[2][w + 1];
    unsigned hhi = s_m[3][w + 1];
    unsigned hpo = s_m[4][w + 1];
    unsigned t2 = hl1 & ~hlo, t3 = hl1 & hlo;
    unsigned p2 = hhi & ~hpo, p3 = hhi & hpo;
    {
        // scan seed: last valid position's (pred_mode, true_mode)
        int vstate = -1;
        if (hv) {
            int lv = 31 - __clz(hv);
            vstate = (((w << 5) + lv) << 2) | ((int)((hpo >> lv) & 1u) << 1) | (int)((hlo >> lv) & 1u);
        }
        int inc = vstate;
#pragma unroll
        for (int d = 1; d < 32; d <<= 1) {
            int o = __shfl_up_sync(0xffffffffu, inc, d);
            if (lane >= d) inc = max(inc, o);
        }
        int wx = __shfl_up_sync(0xffffffffu, inc, 1);
        if (lane == 0) wx = -1;
        if (lane == 31) s_scan[wid] = inc;
        int hb = (t2 ? 1 : 0) | (t3 ? 2 : 0) | (p2 ? 4 : 0) | (p3 ? 8 : 0);
        hb = __reduce_or_sync(0xffffffffu, hb);
        if (lane == 0) s_hasw[wid] = hb;
        __syncthreads();

        // all threads combine the 8 warp totals serially (8 entries)
        int wpre = -1, hs = 0;
#pragma unroll
        for (int ww = 0; ww < NW; ww++) {
            int t = s_scan[ww];
            if (ww < wid) wpre = max(wpre, t);
            hs |= s_hasw[ww];
        }
        const int pstate = max(wx, wpre);

        // ---- sub-phase (a): mode-state sample-and-hold -> q6/q7 (frees U,Ut,P,V) ----
        unsigned q6, q7;
        {
            int pm_in = 0, tm_in = 0;
            if (pstate >= 0) { pm_in = (pstate >> 1) & 1; tm_in = pstate & 1; }
            unsigned long long P0 = ((unsigned long long)hv << 1) | 1ULL;
            unsigned long long P = P0;
            unsigned long long V = ((unsigned long long)(hpo & hv) << 1) | (unsigned long long)pm_in;
            V |= (V << 1) & ~P;  P |= P << 1;
            V |= (V << 2) & ~P;  P |= P << 2;
            V |= (V << 4) & ~P;  P |= P << 4;
            V |= (V << 8) & ~P;  P |= P << 8;
            V |= (V << 16) & ~P; P |= P << 16;
            V |= (V << 32) & ~P;
            unsigned U = (unsigned)V;                 // pred_mode before element e
            P = P0;
            V = ((unsigned long long)(hlo & hv) << 1) | (unsigned long long)tm_in;
            V |= (V << 1) & ~P;  P |= P << 1;
            V |= (V << 2) & ~P;  P |= P << 2;
            V |= (V << 4) & ~P;  P |= P << 4;
            V |= (V << 8) & ~P;  P |= P << 8;
            V |= (V << 16) & ~P; P |= P << 16;
            V |= (V << 32) & ~P;
            unsigned Ut = (unsigned)V;                // true_mode before element e
            q6 = ((p2 & ~U) | (p3 & U)) & hv;                 // BAD  x100
            q7 = ((t2 & Ut & p2) | (t3 & ~Ut & p3)) & hv;     // GOOD x0.1
        }

        // ---- sub-phase (b): radius-5 coverage of pred masks -> q4/q5 ----
        unsigned q4, q5;
        {
            unsigned hip = s_m[3][w], hin = s_m[3][w + 2];
            unsigned pop = s_m[4][w], pon = s_m[4][w + 2];
            unsigned p2p = hip & ~pop, p2n = hin & ~pon;
            unsigned p3p = hip & pop,  p3n = hin & pon;
            unsigned long long C2 = ((unsigned long long)(p2p >> 27)) |
                                    ((unsigned long long)p2 << 5) |
                                    ((unsigned long long)p2n << 37);
            unsigned long long C3 = ((unsigned long long)(p3p >> 27)) |
                                    ((unsigned long long)p3 << 5) |
                                    ((unsigned long long)p3n << 37);
            C2 |= (C2 << 1) | (C2 >> 1);  C2 |= (C2 << 2) | (C2 >> 2);  C2 |= (C2 << 2) | (C2 >> 2);
            C3 |= (C3 << 1) | (C3 >> 1);  C3 |= (C3 << 2) | (C3 >> 2);  C3 |= (C3 << 2) | (C3 >> 2);
            unsigned cv2 = (unsigned)(C2 >> 5), cv3 = (unsigned)(C3 >> 5);
            q4 = ((hs & 4) ? (t2 & ~cv2) : 0u) | ((hs & 8) ? (t3 & ~cv3) : 0u); // x2
            q5 = ((hs & 4) ? 0u : t2) | ((hs & 8) ? 0u : t3);                    // x3
        }

        // ---- sub-phase (c): distance levels -> q0..q3 ----
        unsigned q0, q1, q2, q3;
        {
            unsigned l0p = s_m[1][w], l0n = s_m[1][w + 2];
            unsigned l1p = s_m[2][w], l1n = s_m[2][w + 2];
            unsigned t2p = l1p & ~l0p, t2n = l1n & ~l0n;
            unsigned t3p = l1p & l0p,  t3n = l1n & l0n;
            unsigned long long A2 = ((unsigned long long)(t2p >> 27)) |
                                    ((unsigned long long)t2 << 5) |
                                    ((unsigned long long)t2n << 37);
            unsigned long long A3 = ((unsigned long long)(t3p >> 27)) |
                                    ((unsigned long long)t3 << 5) |
                                    ((unsigned long long)t3n << 37);
            unsigned L0 = ((unsigned)(A2 >> 5) & p2) | ((unsigned)(A3 >> 5) & p3);
            A2 |= (A2 << 1) | (A2 >> 1);  A3 |= (A3 << 1) | (A3 >> 1);
            unsigned L1 = ((unsigned)(A2 >> 5) & p2) | ((unsigned)(A3 >> 5) & p3);
            A2 |= (A2 << 1) | (A2 >> 1);  A3 |= (A3 << 1) | (A3 >> 1);
            unsigned L2 = ((unsigned)(A2 >> 5) & p2) | ((unsigned)(A3 >> 5) & p3);
            A2 |= (A2 << 1) | (A2 >> 1);  A3 |= (A3 << 1) | (A3 >> 1);
            unsigned L3 = ((unsigned)(A2 >> 5) & p2) | ((unsigned)(A3 >> 5) & p3);
            A2 |= (A2 << 1) | (A2 >> 1);  A3 |= (A3 << 1) | (A3 >> 1);
            unsigned L4 = ((unsigned)(A2 >> 5) & p2) | ((unsigned)(A3 >> 5) & p3);
            A2 |= (A2 << 1) | (A2 >> 1);  A3 |= (A3 << 1) | (A3 >> 1);
            unsigned L5 = ((unsigned)(A2 >> 5) & p2) | ((unsigned)(A3 >> 5) & p3);

            // bit-sliced sum of 6 level planes -> 3-bit count
            unsigned x0 = L0 ^ L1 ^ L2;
            unsigned y0 = (L0 & L1) | (L2 & (L0 | L1));
            unsigned x1 = L3 ^ L4 ^ L5;
            unsigned y1 = (L3 & L4) | (L5 & (L3 | L4));
            unsigned pb0 = x0 ^ x1;
            unsigned cc = x0 & x1;
            unsigned pb1 = y0 ^ y1 ^ cc;
            unsigned pb2 = (y0 & y1) | (cc & (y0 | y1));
            unsigned sel = p2 | p3;
            q0 = pb0 | ~sel;
            q1 = pb1 | ~sel;
            q2 = pb2 | ~sel;
            q3 = ((hs & 1) ? 0u : p2) | ((hs & 2) ? 0u : p3);
        }

        // fused MAC: transpose 8 planes -> idx bytes in regs, gather table, FMA
        float acc = 0.0f;
        const float* cep = s_ce + w * 33;
#pragma unroll
        for (int g = 0; g < 4; g++) {
            unsigned s01 = (unsigned)(g | ((g + 4) << 4));
            unsigned A01 = __byte_perm(q0, q1, s01);
            unsigned A23 = __byte_perm(q2, q3, s01);
            unsigned Aw = __byte_perm(A01, A23, 0x5410);
            unsigned B01 = __byte_perm(q4, q5, s01);
            unsigned B23 = __byte_perm(q6, q7, s01);
            unsigned Bw = __byte_perm(B01, B23, 0x5410);
            unsigned long long tg = flipDiag8x8((unsigned long long)Aw | ((unsigned long long)Bw << 32));
            unsigned lo = (unsigned)tg, hi32 = (unsigned)(tg >> 32);
#pragma unroll
            for (int b = 0; b < 4; b++)
                acc += cep[g * 8 + b] * s_tab[(lo >> (8 * b)) & 0xffu];
#pragma unroll
            for (int b = 0; b < 4; b++)
                acc += cep[g * 8 + 4 + b] * s_tab[(hi32 >> (8 * b)) & 0xffu];
        }
        int cnt = __popc(hv);

        // ---- deterministic block reduce ----
#pragma unroll
        for (int d = 16; d > 0; d >>= 1) {
            acc += __shfl_down_sync(0xffffffffu, acc, d);
            cnt += __shfl_down_sync(0xffffffffu, cnt, d);
        }
        if (lane == 0) { s_racc[wid] = acc; s_rcnt[wid] = cnt; }
    }
    __syncthreads();
    if (wid == 0) {
        float a = (lane < NW) ? s_racc[lane] : 0.0f;
        int c = (lane < NW) ? s_rcnt[lane] : 0;
#pragma unroll
        for (int d = 4; d > 0; d >>= 1) {
            a += __shfl_down_sync(0xffffffffu, a, d);
            c += __shfl_down_sync(0xffffffffu, c, d);
        }
        if (lane == 0) {
            g_sum[row] = a; g_cnt[row] = c;
            __threadfence();
            int old = atomicAdd(&g_done, 1);
            s_last = (old == (int)gridDim.x - 1) ? 1 : 0;
        }
    }
    __syncthreads();

    // ---- last block: fixed-order final reduce (resets g_done for graph replay) ----
    if (s_last) {
        float a = 0.0f; int c = 0;
        for (int i = tid; i < B; i += BT) {
            a += __ldcg(&g_sum[i]);
            c += __ldcg(&g_cnt[i]);
        }
#pragma unroll
        for (int d = 16; d > 0; d >>= 1) {
            a += __shfl_down_sync(0xffffffffu, a, d);
            c += __shfl_down_sync(0xffffffffu, c, d);
        }
        if (lane == 0) { s_racc[wid] = a; s_rcnt[wid] = c; }
        __syncthreads();
        if (wid == 0) {
            a = (lane < NW) ? s_racc[lane] : 0.0f;
            c = (lane < NW) ? s_rcnt[lane] : 0;
#pragma unroll
            for (int d = 4; d > 0; d >>= 1) {
                a += __shfl_down_sync(0xffffffffu, a, d);
                c += __shfl_down_sync(0xffffffffu, c, d);
            }
            if (lane == 0) {
                out[0] = a / fmaxf((float)c, 1.0f);
                g_done = 0;
            }
        }
    }
}

extern "C" void kernel_launch(void* const* d_in, const int* in_sizes, int n_in,
                              void* d_out, int out_size)
{
    const float4* logits = (const float4*)d_in[0];
    const int* labels = (const int*)d_in[1];
    int B = in_sizes[1] / SLEN;
    pal_row_kernel<<<B, BT>>>(logits, labels, (float*)d_out, B);
}